// round 12
// baseline (speedup 1.0000x reference)
#include <cuda_runtime.h>
#include <cuda_fp16.h>
#include <cstdint>

#define KN 100000   // batch nodes
#define ME 600000   // edges
#define NT 32768    // time-encoding table samples
#define TLO (-1024.0f)
#define TSTEP 0.0625f
#define TINV 16.0f  // 1/step

// ---------------- scratch (device globals) ----------------------------------
__device__ __half g_yh[(size_t)KN * 512];      // per node: [q | k | v | skip] x128
__device__ __half g_wT[(size_t)5 * 128 * 256]; // transposed fp16 weights [mat][n][k]
__device__ __half g_tab[(size_t)NT * 128];     // cos(s_i * w_k + b_k)  (k-indexed)
__device__ float g_lu[KN];
__device__ float g_denom[KN * 2];

// ---------------- helpers ---------------------------------------------------
__device__ __forceinline__ float poly_cos(float x) {
    float n = rintf(x * 0.3183098861837907f);
    float r = fmaf(n, -3.14159274101257f, x);
    r = fmaf(n, 8.742277657347586e-8f, r);
    float r2 = r * r;
    float p = fmaf(r2, -2.7557319e-7f, 2.4801587e-5f);
    p = fmaf(p, r2, -1.3888889e-3f);
    p = fmaf(p, r2, 4.1666668e-2f);
    p = fmaf(p, r2, -0.5f);
    p = fmaf(p, r2, 1.0f);
    int ni = (int)n;
    return (ni & 1) ? -p : p;
}
__device__ __forceinline__ void mma_f16(float* c, const unsigned* a, const unsigned* b) {
    asm volatile("mma.sync.aligned.m16n8k16.row.col.f32.f16.f16.f32 "
                 "{%0,%1,%2,%3}, {%4,%5,%6,%7}, {%8,%9}, {%0,%1,%2,%3};"
                 : "+f"(c[0]), "+f"(c[1]), "+f"(c[2]), "+f"(c[3])
                 : "r"(a[0]), "r"(a[1]), "r"(a[2]), "r"(a[3]), "r"(b[0]), "r"(b[1]));
}
__device__ __forceinline__ void ldsm_x4(unsigned& r0, unsigned& r1, unsigned& r2, unsigned& r3,
                                        uint32_t addr) {
    asm volatile("ldmatrix.sync.aligned.m8n8.x4.shared.b16 {%0,%1,%2,%3}, [%4];"
                 : "=r"(r0), "=r"(r1), "=r"(r2), "=r"(r3) : "r"(addr));
}
__device__ __forceinline__ unsigned pkh2(float a, float b) {
    half2 h = __floats2half2_rn(a, b);
    return *(unsigned*)&h;
}
__device__ __forceinline__ float2 uph2(unsigned u) {
    return __half22float2(*(half2*)&u);
}
__device__ __forceinline__ uint32_t smem_u32(const void* p) {
    uint32_t a;
    asm("{ .reg .u64 t; cvta.to.shared.u64 t, %1; cvt.u32.u64 %0, t; }" : "=r"(a) : "l"(p));
    return a;
}

// ---------------- prep: transpose+convert weights to fp16 -------------------
__global__ void k_prep(const float* __restrict__ W0, const float* __restrict__ W1,
                       const float* __restrict__ W2, const float* __restrict__ W3,
                       const float* __restrict__ W4) {
    int i = blockIdx.x * 256 + threadIdx.x;
    if (i >= 5 * 32768) return;
    int mat = i >> 15, rem = i & 32767;
    int k = rem >> 7, n = rem & 127;
    const float* src = (mat == 0) ? W0 : (mat == 1) ? W1 : (mat == 2) ? W2 : (mat == 3) ? W3 : W4;
    g_wT[((size_t)mat * 128 + n) * 256 + k] = __float2half_rn(src[rem]);
}

// ---------------- table: g_tab[i][k] = cos(s_i * w_k + b_k) -----------------
__global__ void k_tab(const float* __restrict__ w_t, const float* __restrict__ b_t) {
    int i = blockIdx.x * 256 + threadIdx.x;
    if (i >= NT * 128) return;
    int row = i >> 7, k = i & 127;
    float s = TLO + (float)row * TSTEP;
    g_tab[i] = __float2half_rn(poly_cos(fmaf(s, w_t[k], b_t[k])));
}

// ---------------- init: zero out/denom, gather last_update ------------------
__global__ void k_init(float* __restrict__ out,
                       const float* __restrict__ last_update,
                       const int* __restrict__ n_id) {
    int i = blockIdx.x * 256 + threadIdx.x;
    if (i < KN * 128) out[i] = 0.f;
    if (i < KN * 2) g_denom[i] = 0.f;
    if (i < KN) g_lu[i] = last_update[n_id[i]];
}

// ============================================================================
// fp16 GEMM core: BK=16 tile as [kh(2)][row(128)][8 halves]; kh stride 2048B.
// Warp tile 64x32; warps 2(m)x4(n); fragments via ldmatrix.x4.
// ============================================================================
__device__ __forceinline__ void gemm_compute_ldsm(uint32_t As, uint32_t Bs,
                                                  int row_base, int col_base,
                                                  int lane, float c[4][4][4]) {
    unsigned a[4][4], b[4][2];
    uint32_t l7 = lane & 7;
    uint32_t baddr = Bs + (uint32_t)(col_base + (lane >> 3) * 8 + l7) * 16u;
    ldsm_x4(b[0][0], b[1][0], b[2][0], b[3][0], baddr);
    ldsm_x4(b[0][1], b[1][1], b[2][1], b[3][1], baddr + 2048u);
    uint32_t arow = (uint32_t)(row_base + ((lane >> 3) & 1) * 8 + l7);
    uint32_t abase = As + ((uint32_t)(lane >> 4)) * 2048u + arow * 16u;
#pragma unroll
    for (int mt = 0; mt < 4; mt++)
        ldsm_x4(a[mt][0], a[mt][1], a[mt][2], a[mt][3], abase + (uint32_t)mt * 256u);
#pragma unroll
    for (int mt = 0; mt < 4; mt++)
#pragma unroll
        for (int nt = 0; nt < 4; nt++) mma_f16(c[mt][nt], a[mt], b[nt]);
}

// ---------------- fused node GEMM: all 4 weight matrices, A smem-resident ---
struct NodeB { const float* b[4]; };

__global__ __launch_bounds__(256, 2) void k_node_fused(const int* __restrict__ n_id,
                                                       const float* __restrict__ memv,
                                                       const float* __restrict__ feat,
                                                       NodeB pb) {
    extern __shared__ __align__(16) char dsm[];
    __half* Asm = (__half*)dsm;                    // 16 ktiles x 4KB = 64KB
    __half* Bsm = (__half*)(dsm + 65536);          // 2 x 4KB double buffer
    __shared__ int nid_s[128];
    const int m0 = blockIdx.x * 128;
    const int tid = threadIdx.x;
    int rows = KN - m0; if (rows > 128) rows = 128;
    if (tid < 128) nid_s[tid] = n_id[m0 + (tid < rows ? tid : rows - 1)];
    __syncthreads();

    const int warp = tid >> 5, lane = tid & 31;
    const int wm = warp & 1, wn = warp >> 1;
    const int row_base = wm * 64, col_base = wn * 32;
    const int lr = lane >> 2, lc = lane & 3;
    const int trow = tid & 127, tkh = tid >> 7;

    {
        const int nid_a = nid_s[trow];
        const float* arow_mem = &memv[(size_t)nid_a * 128];
        const float* arow_feat = &feat[(size_t)nid_a * 128];
#pragma unroll
        for (int kt = 0; kt < 16; kt++) {
            int col = kt * 16 + tkh * 8;
            const float* srcrow = (col < 128) ? (arow_mem + col) : (arow_feat + col - 128);
            float4 v0 = *(const float4*)srcrow;
            float4 v1 = *(const float4*)(srcrow + 4);
            uint4 pa;
            pa.x = pkh2(v0.x, v0.y); pa.y = pkh2(v0.z, v0.w);
            pa.z = pkh2(v1.x, v1.y); pa.w = pkh2(v1.z, v1.w);
            *(uint4*)&Asm[(size_t)kt * 2048 + tkh * 1024 + trow * 8] = pa;
        }
    }

    uint32_t as0 = smem_u32(Asm), bs0 = smem_u32(Bsm);
    float c[4][4][4];
#pragma unroll
    for (int mt = 0; mt < 4; mt++)
#pragma unroll
        for (int nt = 0; nt < 4; nt++)
#pragma unroll
            for (int i = 0; i < 4; i++) c[mt][nt][i] = 0.f;

    uint4 bpre;
    auto load_b = [&](int step) {
        int wt = step >> 4, kt = step & 15;
        bpre = *(const uint4*)&g_wT[(size_t)wt * 32768 + (size_t)trow * 256 + kt * 16 + tkh * 8];
    };
    auto store_b = [&](int buf) {
        *(uint4*)&Bsm[(size_t)buf * 2048 + tkh * 1024 + trow * 8] = bpre;
    };

    load_b(0);
    store_b(0);
    __syncthreads();

    for (int wt = 0; wt < 4; wt++) {
        for (int kt = 0; kt < 16; kt++) {
            int step = wt * 16 + kt;
            int buf = step & 1;
            if (step < 63) load_b(step + 1);
            gemm_compute_ldsm(as0 + (uint32_t)kt * 4096u, bs0 + (uint32_t)buf * 4096u,
                              row_base, col_base, lane, c);
            if (step < 63) { store_b(buf ^ 1); __syncthreads(); }
        }
        const float* bias = pb.b[wt];
#pragma unroll
        for (int nt = 0; nt < 4; nt++) {
            int col = col_base + nt * 8 + lc * 2;
            float2 bb = *(const float2*)&bias[col];
#pragma unroll
            for (int mt = 0; mt < 4; mt++) {
                int r0 = row_base + mt * 16 + lr;
                if (r0 < rows)
                    *(unsigned*)&g_yh[(size_t)(m0 + r0) * 512 + wt * 128 + col] =
                        pkh2(c[mt][nt][0] + bb.x, c[mt][nt][1] + bb.y);
                if (r0 + 8 < rows)
                    *(unsigned*)&g_yh[(size_t)(m0 + r0 + 8) * 512 + wt * 128 + col] =
                        pkh2(c[mt][nt][2] + bb.x, c[mt][nt][3] + bb.y);
                c[mt][nt][0] = 0.f; c[mt][nt][1] = 0.f; c[mt][nt][2] = 0.f; c[mt][nt][3] = 0.f;
            }
        }
    }
}

// ---------------- fused edge GEMM + attention --------------------------------
// SMEM: Bsm resident 64KB (dies after mainloop; e-stage overlays it) + A 2x4KB.
__global__ __launch_bounds__(256, 2) void k_edge_attn(const int* __restrict__ src_a,
                                                      const int* __restrict__ dst_a,
                                                      const int* __restrict__ e_id,
                                                      const float* __restrict__ edge_t,
                                                      const float* __restrict__ eraw,
                                                      float* __restrict__ out) {
    extern __shared__ __align__(16) char dsm[];
    __half* Bsm = (__half*)dsm;                    // 16 ktiles x 4KB = 64KB (resident)
    __half* Esm = (__half*)dsm;                    // e-stage 128x128 fp16 = 32KB (overlay)
    __half* Asm = (__half*)(dsm + 65536);          // 2 x 4KB double buffer
    __shared__ int eid_s[128], src_s[128], dst_s[128];
    __shared__ float relt_s[128];
    const int m0 = blockIdx.x * 128;
    const int tid = threadIdx.x;
    int rows = ME - m0; if (rows > 128) rows = 128;
    if (tid < 128) {
        int r = (tid < rows ? tid : rows - 1);
        int e = e_id[m0 + r];
        int s = src_a[m0 + r];
        eid_s[tid] = e;
        src_s[tid] = s;
        dst_s[tid] = dst_a[m0 + r];
        relt_s[tid] = edge_t[e] - g_lu[s];
    }

    const int warp = tid >> 5, lane = tid & 31;
    const int wm = warp & 1, wn = warp >> 1;
    const int row_base = wm * 64, col_base = wn * 32;
    const int lr = lane >> 2, lc = lane & 3;
    const int trow = tid & 127, tkh = tid >> 7;

    // Load B (We) resident: 16 ktiles
    {
        const __half* brow = &g_wT[(size_t)4 * 32768 + (size_t)trow * 256 + tkh * 8];
#pragma unroll
        for (int kt = 0; kt < 16; kt++)
            *(uint4*)&Bsm[(size_t)kt * 2048 + tkh * 1024 + trow * 8] =
                *(const uint4*)(brow + kt * 16);
    }
    __syncthreads();

    float c[4][4][4];
#pragma unroll
    for (int mt = 0; mt < 4; mt++)
#pragma unroll
        for (int nt = 0; nt < 4; nt++)
#pragma unroll
            for (int i = 0; i < 4; i++) c[mt][nt][i] = 0.f;

    float x = (relt_s[trow] - TLO) * TINV;
    x = fminf(fmaxf(x, 0.0f), (float)(NT - 1) - 1e-3f);
    const int ti = (int)x;
    const float tf = x - (float)ti;
    const __half* trow0 = &g_tab[(size_t)ti * 128];
    const float* arow_msg = &eraw[(size_t)eid_s[trow] * 128];
    uint32_t as0 = smem_u32(Asm), bs0 = smem_u32(Bsm);

    float apre[8];
    auto load_a = [&](int ch, float* ap) {
        int col = ch * 16 + tkh * 8;
        if (col < 128) {
            uint4 u0 = *(const uint4*)(trow0 + col);
            uint4 u1 = *(const uint4*)(trow0 + 128 + col);
            float2 a0 = uph2(u0.x), a1 = uph2(u0.y), a2 = uph2(u0.z), a3 = uph2(u0.w);
            float2 b0 = uph2(u1.x), b1 = uph2(u1.y), b2 = uph2(u1.z), b3 = uph2(u1.w);
            ap[0] = fmaf(tf, b0.x - a0.x, a0.x); ap[1] = fmaf(tf, b0.y - a0.y, a0.y);
            ap[2] = fmaf(tf, b1.x - a1.x, a1.x); ap[3] = fmaf(tf, b1.y - a1.y, a1.y);
            ap[4] = fmaf(tf, b2.x - a2.x, a2.x); ap[5] = fmaf(tf, b2.y - a2.y, a2.y);
            ap[6] = fmaf(tf, b3.x - a3.x, a3.x); ap[7] = fmaf(tf, b3.y - a3.y, a3.y);
        } else {
            const float* srcrow = arow_msg + (col - 128);
            float4 v0 = *(const float4*)srcrow;
            float4 v1 = *(const float4*)(srcrow + 4);
            ap[0] = v0.x; ap[1] = v0.y; ap[2] = v0.z; ap[3] = v0.w;
            ap[4] = v1.x; ap[5] = v1.y; ap[6] = v1.z; ap[7] = v1.w;
        }
    };
    auto store_a = [&](int buf, const float* ap) {
        uint4 pa;
        pa.x = pkh2(ap[0], ap[1]); pa.y = pkh2(ap[2], ap[3]);
        pa.z = pkh2(ap[4], ap[5]); pa.w = pkh2(ap[6], ap[7]);
        *(uint4*)&Asm[(size_t)buf * 2048 + tkh * 1024 + trow * 8] = pa;
    };

    load_a(0, apre);
    store_a(0, apre);
    __syncthreads();
    for (int ch = 0; ch < 16; ch++) {
        int buf = ch & 1;
        if (ch < 15) load_a(ch + 1, apre);
        gemm_compute_ldsm(as0 + (uint32_t)buf * 4096u, bs0 + (uint32_t)ch * 4096u,
                          row_base, col_base, lane, c);
        if (ch < 15) { store_a(buf ^ 1, apre); __syncthreads(); }
    }

    // stage e tile to SMEM (overlays dead B region) ---------------------------
    __syncthreads();   // all warps done reading Bsm
#pragma unroll
    for (int nt = 0; nt < 4; nt++) {
        int col = col_base + nt * 8 + lc * 2;
#pragma unroll
        for (int mt = 0; mt < 4; mt++) {
            int r0 = row_base + mt * 16 + lr;
            *(unsigned*)&Esm[(size_t)r0 * 128 + col] = pkh2(c[mt][nt][0], c[mt][nt][1]);
            *(unsigned*)&Esm[(size_t)(r0 + 8) * 128 + col] = pkh2(c[mt][nt][2], c[mt][nt][3]);
        }
    }
    __syncthreads();

    // attention phase: each warp handles 16 edges -----------------------------
    for (int i = 0; i < 16; i++) {
        int el = warp * 16 + i;
        if (el >= rows) break;
        int s = src_s[el], d = dst_s[el];
        uint2 qu = *(const uint2*)&g_yh[(size_t)d * 512 + lane * 4];
        uint2 ku = *(const uint2*)&g_yh[(size_t)s * 512 + 128 + lane * 4];
        uint2 vu = *(const uint2*)&g_yh[(size_t)s * 512 + 256 + lane * 4];
        uint2 eu = *(const uint2*)&Esm[(size_t)el * 128 + lane * 4];
        float2 q0 = uph2(qu.x), q1 = uph2(qu.y);
        float2 k0 = uph2(ku.x), k1 = uph2(ku.y);
        float2 v0 = uph2(vu.x), v1 = uph2(vu.y);
        float2 e0 = uph2(eu.x), e1 = uph2(eu.y);
        float ke0x = k0.x + e0.x, ke0y = k0.y + e0.y;
        float ke1x = k1.x + e1.x, ke1y = k1.y + e1.y;
        float p = q0.x * ke0x + q0.y * ke0y + q1.x * ke1x + q1.y * ke1y;
        p += __shfl_xor_sync(0xffffffffu, p, 8);
        p += __shfl_xor_sync(0xffffffffu, p, 4);
        p += __shfl_xor_sync(0xffffffffu, p, 2);
        p += __shfl_xor_sync(0xffffffffu, p, 1);
        float alpha = __expf(p * 0.125f);   // 1/sqrt(64)
        if ((lane & 15) == 0) atomicAdd(&g_denom[d * 2 + (lane >> 4)], alpha);
        float4 o = make_float4(alpha * (v0.x + e0.x), alpha * (v0.y + e0.y),
                               alpha * (v1.x + e1.x), alpha * (v1.y + e1.y));
        float* dptr = &out[(size_t)d * 128 + lane * 4];
        asm volatile("red.global.add.v4.f32 [%0], {%1,%2,%3,%4};"
                     :: "l"(dptr), "f"(o.x), "f"(o.y), "f"(o.z), "f"(o.w) : "memory");
    }
}

// ---------------- finalize: out = out/denom + skip --------------------------
__global__ void k_final(float* __restrict__ out) {
    int i = blockIdx.x * 256 + threadIdx.x;
    if (i >= KN * 32) return;
    int node = i >> 5;
    int j4 = (i & 31) * 4;
    int h = j4 >> 6;
    float den = g_denom[node * 2 + h];
    float inv = den > 0.f ? 1.f / den : 0.f;
    float4 u = *(float4*)&out[(size_t)node * 128 + j4];
    uint2 sku = *(const uint2*)&g_yh[(size_t)node * 512 + 384 + j4];
    float2 s0 = uph2(sku.x), s1 = uph2(sku.y);
    u.x = u.x * inv + s0.x;
    u.y = u.y * inv + s0.y;
    u.z = u.z * inv + s1.x;
    u.w = u.w * inv + s1.y;
    *(float4*)&out[(size_t)node * 128 + j4] = u;
}

// ---------------- launch -----------------------------------------------------
#define NODE_SMEM (65536 + 8192)
#define EDGE_SMEM (65536 + 8192)

extern "C" void kernel_launch(void* const* d_in, const int* in_sizes, int n_in,
                              void* d_out, int out_size) {
    (void)in_sizes; (void)n_in; (void)out_size;
    const int*   n_id    = (const int*)d_in[0];
    const int*   eib     = (const int*)d_in[1];   // [2, M]: src then dst
    const int*   e_id    = (const int*)d_in[2];
    const float* nfeat   = (const float*)d_in[4];
    const float* eraw    = (const float*)d_in[5];
    const float* edge_t  = (const float*)d_in[6];
    const float* memv    = (const float*)d_in[7];
    const float* last_up = (const float*)d_in[8];
    const float* w_t     = (const float*)d_in[9];
    const float* b_t     = (const float*)d_in[10];
    const float* Wq = (const float*)d_in[11];
    const float* Wk = (const float*)d_in[13];
    const float* Wv = (const float*)d_in[15];
    const float* We = (const float*)d_in[17];
    const float* Wskip = (const float*)d_in[18];
    NodeB pb;
    pb.b[0] = (const float*)d_in[12];
    pb.b[1] = (const float*)d_in[14];
    pb.b[2] = (const float*)d_in[16];
    pb.b[3] = (const float*)d_in[19];
    float* out = (float*)d_out;

    cudaFuncSetAttribute(k_node_fused, cudaFuncAttributeMaxDynamicSharedMemorySize, NODE_SMEM);
    cudaFuncSetAttribute(k_edge_attn, cudaFuncAttributeMaxDynamicSharedMemorySize, EDGE_SMEM);

    k_prep<<<(5 * 32768 + 255) / 256, 256>>>(Wq, Wk, Wv, Wskip, We);
    k_tab<<<(NT * 128 + 255) / 256, 256>>>(w_t, b_t);
    k_init<<<(KN * 128 + 255) / 256, 256>>>(out, last_up, n_id);
    k_node_fused<<<(KN + 127) / 128, 256, NODE_SMEM>>>(n_id, memv, nfeat, pb);
    k_edge_attn<<<(ME + 127) / 128, 256, EDGE_SMEM>>>(eib, eib + ME, e_id, edge_t, eraw, out);
    k_final<<<(KN * 32 + 255) / 256, 256>>>(out);
}

// round 13
// speedup vs baseline: 1.0750x; 1.0750x over previous
#include <cuda_runtime.h>
#include <cuda_fp16.h>
#include <cstdint>

#define KN 100000   // batch nodes
#define ME 600000   // edges
#define NT 32768    // time-encoding table samples
#define TLO (-1024.0f)
#define TSTEP 0.0625f
#define TINV 16.0f  // 1/step

// ---------------- scratch (device globals) ----------------------------------
__device__ __half g_yh[(size_t)KN * 512];      // per node: [q | k | v | skip] x128
__device__ __half g_eh[(size_t)ME * 128];      // per edge: e = edge_attr @ We
__device__ __half g_wT[(size_t)5 * 128 * 256]; // transposed fp16 weights [mat][n][k]
__device__ __half g_tab[(size_t)NT * 128];     // cos(s_i * w_k + b_k)  (k-indexed)
__device__ float g_lu[KN];
__device__ float g_denom[KN * 2];

// ---------------- helpers ---------------------------------------------------
__device__ __forceinline__ float poly_cos(float x) {
    float n = rintf(x * 0.3183098861837907f);
    float r = fmaf(n, -3.14159274101257f, x);
    r = fmaf(n, 8.742277657347586e-8f, r);
    float r2 = r * r;
    float p = fmaf(r2, -2.7557319e-7f, 2.4801587e-5f);
    p = fmaf(p, r2, -1.3888889e-3f);
    p = fmaf(p, r2, 4.1666668e-2f);
    p = fmaf(p, r2, -0.5f);
    p = fmaf(p, r2, 1.0f);
    int ni = (int)n;
    return (ni & 1) ? -p : p;
}
__device__ __forceinline__ void mma_f16(float* c, const unsigned* a, const unsigned* b) {
    asm volatile("mma.sync.aligned.m16n8k16.row.col.f32.f16.f16.f32 "
                 "{%0,%1,%2,%3}, {%4,%5,%6,%7}, {%8,%9}, {%0,%1,%2,%3};"
                 : "+f"(c[0]), "+f"(c[1]), "+f"(c[2]), "+f"(c[3])
                 : "r"(a[0]), "r"(a[1]), "r"(a[2]), "r"(a[3]), "r"(b[0]), "r"(b[1]));
}
__device__ __forceinline__ void ldsm_x4(unsigned& r0, unsigned& r1, unsigned& r2, unsigned& r3,
                                        uint32_t addr) {
    asm volatile("ldmatrix.sync.aligned.m8n8.x4.shared.b16 {%0,%1,%2,%3}, [%4];"
                 : "=r"(r0), "=r"(r1), "=r"(r2), "=r"(r3) : "r"(addr));
}
__device__ __forceinline__ unsigned pkh2(float a, float b) {
    half2 h = __floats2half2_rn(a, b);
    return *(unsigned*)&h;
}
__device__ __forceinline__ float2 uph2(unsigned u) {
    return __half22float2(*(half2*)&u);
}
__device__ __forceinline__ uint32_t smem_u32(const void* p) {
    uint32_t a;
    asm("{ .reg .u64 t; cvta.to.shared.u64 t, %1; cvt.u32.u64 %0, t; }" : "=r"(a) : "l"(p));
    return a;
}

// ---------------- prep: transpose+convert weights to fp16 -------------------
__global__ void k_prep(const float* __restrict__ W0, const float* __restrict__ W1,
                       const float* __restrict__ W2, const float* __restrict__ W3,
                       const float* __restrict__ W4) {
    int i = blockIdx.x * 256 + threadIdx.x;
    if (i >= 5 * 32768) return;
    int mat = i >> 15, rem = i & 32767;
    int k = rem >> 7, n = rem & 127;
    const float* src = (mat == 0) ? W0 : (mat == 1) ? W1 : (mat == 2) ? W2 : (mat == 3) ? W3 : W4;
    g_wT[((size_t)mat * 128 + n) * 256 + k] = __float2half_rn(src[rem]);
}

// ---------------- table: g_tab[i][k] = cos(s_i * w_k + b_k) -----------------
__global__ void k_tab(const float* __restrict__ w_t, const float* __restrict__ b_t) {
    int i = blockIdx.x * 256 + threadIdx.x;
    if (i >= NT * 128) return;
    int row = i >> 7, k = i & 127;
    float s = TLO + (float)row * TSTEP;
    g_tab[i] = __float2half_rn(poly_cos(fmaf(s, w_t[k], b_t[k])));
}

// ---------------- init: zero out/denom, gather last_update ------------------
__global__ void k_init(float* __restrict__ out,
                       const float* __restrict__ last_update,
                       const int* __restrict__ n_id) {
    int i = blockIdx.x * 256 + threadIdx.x;
    if (i < KN * 128) out[i] = 0.f;
    if (i < KN * 2) g_denom[i] = 0.f;
    if (i < KN) g_lu[i] = last_update[n_id[i]];
}

// ============================================================================
// fp16 GEMM core: BK=16 tile as [kh(2)][row(128)][8 halves]; kh stride 2048B.
// Warp tile 64x32; warps 2(m)x4(n); fragments via ldmatrix.x4.
// ============================================================================
__device__ __forceinline__ void gemm_compute_ldsm(uint32_t As, uint32_t Bs,
                                                  int row_base, int col_base,
                                                  int lane, float c[4][4][4]) {
    unsigned a[4][4], b[4][2];
    uint32_t l7 = lane & 7;
    uint32_t baddr = Bs + (uint32_t)(col_base + (lane >> 3) * 8 + l7) * 16u;
    ldsm_x4(b[0][0], b[1][0], b[2][0], b[3][0], baddr);
    ldsm_x4(b[0][1], b[1][1], b[2][1], b[3][1], baddr + 2048u);
    uint32_t arow = (uint32_t)(row_base + ((lane >> 3) & 1) * 8 + l7);
    uint32_t abase = As + ((uint32_t)(lane >> 4)) * 2048u + arow * 16u;
#pragma unroll
    for (int mt = 0; mt < 4; mt++)
        ldsm_x4(a[mt][0], a[mt][1], a[mt][2], a[mt][3], abase + (uint32_t)mt * 256u);
#pragma unroll
    for (int mt = 0; mt < 4; mt++)
#pragma unroll
        for (int nt = 0; nt < 4; nt++) mma_f16(c[mt][nt], a[mt], b[nt]);
}

// ---------------- fused node GEMM: all 4 weight matrices, A smem-resident ---
struct NodeB { const float* b[4]; };

__global__ __launch_bounds__(256, 2) void k_node_fused(const int* __restrict__ n_id,
                                                       const float* __restrict__ memv,
                                                       const float* __restrict__ feat,
                                                       NodeB pb) {
    extern __shared__ __align__(16) char dsm[];
    __half* Asm = (__half*)dsm;                    // 16 ktiles x 4KB = 64KB
    __half* Bsm = (__half*)(dsm + 65536);          // 2 x 4KB double buffer
    __shared__ int nid_s[128];
    const int m0 = blockIdx.x * 128;
    const int tid = threadIdx.x;
    int rows = KN - m0; if (rows > 128) rows = 128;
    if (tid < 128) nid_s[tid] = n_id[m0 + (tid < rows ? tid : rows - 1)];
    __syncthreads();

    const int warp = tid >> 5, lane = tid & 31;
    const int wm = warp & 1, wn = warp >> 1;
    const int row_base = wm * 64, col_base = wn * 32;
    const int lr = lane >> 2, lc = lane & 3;
    const int trow = tid & 127, tkh = tid >> 7;

    {
        const int nid_a = nid_s[trow];
        const float* arow_mem = &memv[(size_t)nid_a * 128];
        const float* arow_feat = &feat[(size_t)nid_a * 128];
#pragma unroll
        for (int kt = 0; kt < 16; kt++) {
            int col = kt * 16 + tkh * 8;
            const float* srcrow = (col < 128) ? (arow_mem + col) : (arow_feat + col - 128);
            float4 v0 = *(const float4*)srcrow;
            float4 v1 = *(const float4*)(srcrow + 4);
            uint4 pa;
            pa.x = pkh2(v0.x, v0.y); pa.y = pkh2(v0.z, v0.w);
            pa.z = pkh2(v1.x, v1.y); pa.w = pkh2(v1.z, v1.w);
            *(uint4*)&Asm[(size_t)kt * 2048 + tkh * 1024 + trow * 8] = pa;
        }
    }

    uint32_t as0 = smem_u32(Asm), bs0 = smem_u32(Bsm);
    float c[4][4][4];
#pragma unroll
    for (int mt = 0; mt < 4; mt++)
#pragma unroll
        for (int nt = 0; nt < 4; nt++)
#pragma unroll
            for (int i = 0; i < 4; i++) c[mt][nt][i] = 0.f;

    uint4 bpre;
    auto load_b = [&](int step) {
        int wt = step >> 4, kt = step & 15;
        bpre = *(const uint4*)&g_wT[(size_t)wt * 32768 + (size_t)trow * 256 + kt * 16 + tkh * 8];
    };
    auto store_b = [&](int buf) {
        *(uint4*)&Bsm[(size_t)buf * 2048 + tkh * 1024 + trow * 8] = bpre;
    };

    load_b(0);
    store_b(0);
    __syncthreads();

    for (int wt = 0; wt < 4; wt++) {
        for (int kt = 0; kt < 16; kt++) {
            int step = wt * 16 + kt;
            int buf = step & 1;
            if (step < 63) load_b(step + 1);
            gemm_compute_ldsm(as0 + (uint32_t)kt * 4096u, bs0 + (uint32_t)buf * 4096u,
                              row_base, col_base, lane, c);
            if (step < 63) { store_b(buf ^ 1); __syncthreads(); }
        }
        const float* bias = pb.b[wt];
#pragma unroll
        for (int nt = 0; nt < 4; nt++) {
            int col = col_base + nt * 8 + lc * 2;
            float2 bb = *(const float2*)&bias[col];
#pragma unroll
            for (int mt = 0; mt < 4; mt++) {
                int r0 = row_base + mt * 16 + lr;
                if (r0 < rows)
                    *(unsigned*)&g_yh[(size_t)(m0 + r0) * 512 + wt * 128 + col] =
                        pkh2(c[mt][nt][0] + bb.x, c[mt][nt][1] + bb.y);
                if (r0 + 8 < rows)
                    *(unsigned*)&g_yh[(size_t)(m0 + r0 + 8) * 512 + wt * 128 + col] =
                        pkh2(c[mt][nt][2] + bb.x, c[mt][nt][3] + bb.y);
                c[mt][nt][0] = 0.f; c[mt][nt][1] = 0.f; c[mt][nt][2] = 0.f; c[mt][nt][3] = 0.f;
            }
        }
    }
}

// ---------------- edge GEMM: B (We) SMEM-resident, A streamed ---------------
__global__ __launch_bounds__(256, 2) void k_edge_gemm(const int* __restrict__ src_a,
                                                      const int* __restrict__ e_id,
                                                      const float* __restrict__ edge_t,
                                                      const float* __restrict__ eraw) {
    extern __shared__ __align__(16) char dsm[];
    __half* Bsm = (__half*)dsm;                    // 16 ktiles x 4KB = 64KB (resident)
    __half* Asm = (__half*)(dsm + 65536);          // 2 x 4KB double buffer
    __shared__ int eid_s[128];
    __shared__ float relt_s[128];
    const int m0 = blockIdx.x * 128;
    const int tid = threadIdx.x;
    int rows = ME - m0; if (rows > 128) rows = 128;
    if (tid < 128) {
        int r = (tid < rows ? tid : rows - 1);
        int e = e_id[m0 + r];
        eid_s[tid] = e;
        relt_s[tid] = edge_t[e] - g_lu[src_a[m0 + r]];
    }

    const int warp = tid >> 5, lane = tid & 31;
    const int wm = warp & 1, wn = warp >> 1;
    const int row_base = wm * 64, col_base = wn * 32;
    const int lr = lane >> 2, lc = lane & 3;
    const int trow = tid & 127, tkh = tid >> 7;

    // Load B (We) resident: 16 ktiles
    {
        const __half* brow = &g_wT[(size_t)4 * 32768 + (size_t)trow * 256 + tkh * 8];
#pragma unroll
        for (int kt = 0; kt < 16; kt++)
            *(uint4*)&Bsm[(size_t)kt * 2048 + tkh * 1024 + trow * 8] =
                *(const uint4*)(brow + kt * 16);
    }
    __syncthreads();

    float c[4][4][4];
#pragma unroll
    for (int mt = 0; mt < 4; mt++)
#pragma unroll
        for (int nt = 0; nt < 4; nt++)
#pragma unroll
            for (int i = 0; i < 4; i++) c[mt][nt][i] = 0.f;

    float x = (relt_s[trow] - TLO) * TINV;
    x = fminf(fmaxf(x, 0.0f), (float)(NT - 1) - 1e-3f);
    const int ti = (int)x;
    const float tf = x - (float)ti;
    const __half* trow0 = &g_tab[(size_t)ti * 128];
    const float* arow_msg = &eraw[(size_t)eid_s[trow] * 128];
    uint32_t as0 = smem_u32(Asm), bs0 = smem_u32(Bsm);

    float apre[8];
    auto load_a = [&](int ch, float* ap) {
        int col = ch * 16 + tkh * 8;
        if (col < 128) {
            uint4 u0 = *(const uint4*)(trow0 + col);
            uint4 u1 = *(const uint4*)(trow0 + 128 + col);
            float2 a0 = uph2(u0.x), a1 = uph2(u0.y), a2 = uph2(u0.z), a3 = uph2(u0.w);
            float2 b0 = uph2(u1.x), b1 = uph2(u1.y), b2 = uph2(u1.z), b3 = uph2(u1.w);
            ap[0] = fmaf(tf, b0.x - a0.x, a0.x); ap[1] = fmaf(tf, b0.y - a0.y, a0.y);
            ap[2] = fmaf(tf, b1.x - a1.x, a1.x); ap[3] = fmaf(tf, b1.y - a1.y, a1.y);
            ap[4] = fmaf(tf, b2.x - a2.x, a2.x); ap[5] = fmaf(tf, b2.y - a2.y, a2.y);
            ap[6] = fmaf(tf, b3.x - a3.x, a3.x); ap[7] = fmaf(tf, b3.y - a3.y, a3.y);
        } else {
            const float* srcrow = arow_msg + (col - 128);
            float4 v0 = *(const float4*)srcrow;
            float4 v1 = *(const float4*)(srcrow + 4);
            ap[0] = v0.x; ap[1] = v0.y; ap[2] = v0.z; ap[3] = v0.w;
            ap[4] = v1.x; ap[5] = v1.y; ap[6] = v1.z; ap[7] = v1.w;
        }
    };
    auto store_a = [&](int buf, const float* ap) {
        uint4 pa;
        pa.x = pkh2(ap[0], ap[1]); pa.y = pkh2(ap[2], ap[3]);
        pa.z = pkh2(ap[4], ap[5]); pa.w = pkh2(ap[6], ap[7]);
        *(uint4*)&Asm[(size_t)buf * 2048 + tkh * 1024 + trow * 8] = pa;
    };

    load_a(0, apre);
    store_a(0, apre);
    __syncthreads();
    for (int ch = 0; ch < 16; ch++) {
        int buf = ch & 1;
        if (ch < 15) load_a(ch + 1, apre);
        gemm_compute_ldsm(as0 + (uint32_t)buf * 4096u, bs0 + (uint32_t)ch * 4096u,
                          row_base, col_base, lane, c);
        if (ch < 15) { store_a(buf ^ 1, apre); __syncthreads(); }
    }

#pragma unroll
    for (int nt = 0; nt < 4; nt++) {
        int col = col_base + nt * 8 + lc * 2;
#pragma unroll
        for (int mt = 0; mt < 4; mt++) {
            int r0 = row_base + mt * 16 + lr;
            if (r0 < rows)
                *(unsigned*)&g_eh[(size_t)(m0 + r0) * 128 + col] =
                    pkh2(c[mt][nt][0], c[mt][nt][1]);
            if (r0 + 8 < rows)
                *(unsigned*)&g_eh[(size_t)(m0 + r0 + 8) * 128 + col] =
                    pkh2(c[mt][nt][2], c[mt][nt][3]);
        }
    }
}

// ---------------- fused attention (fp16 inputs, fp32 math/accum) ------------
__global__ __launch_bounds__(256) void k_attn(const int* __restrict__ src_a,
                                              const int* __restrict__ dst_a,
                                              float* __restrict__ out) {
    int gw = (blockIdx.x * 256 + threadIdx.x) >> 5;
    int lane = threadIdx.x & 31;
    if (gw >= ME) return;
    int s = src_a[gw], d = dst_a[gw];
    uint2 qu = *(const uint2*)&g_yh[(size_t)d * 512 + lane * 4];
    uint2 ku = *(const uint2*)&g_yh[(size_t)s * 512 + 128 + lane * 4];
    uint2 vu = *(const uint2*)&g_yh[(size_t)s * 512 + 256 + lane * 4];
    uint2 eu = *(const uint2*)&g_eh[(size_t)gw * 128 + lane * 4];
    float2 q0 = uph2(qu.x), q1 = uph2(qu.y);
    float2 k0 = uph2(ku.x), k1 = uph2(ku.y);
    float2 v0 = uph2(vu.x), v1 = uph2(vu.y);
    float2 e0 = uph2(eu.x), e1 = uph2(eu.y);
    float ke0x = k0.x + e0.x, ke0y = k0.y + e0.y, ke1x = k1.x + e1.x, ke1y = k1.y + e1.y;
    float p = q0.x * ke0x + q0.y * ke0y + q1.x * ke1x + q1.y * ke1y;
    p += __shfl_xor_sync(0xffffffffu, p, 8);
    p += __shfl_xor_sync(0xffffffffu, p, 4);
    p += __shfl_xor_sync(0xffffffffu, p, 2);
    p += __shfl_xor_sync(0xffffffffu, p, 1);
    float alpha = __expf(p * 0.125f);   // 1/sqrt(64)
    if ((lane & 15) == 0) atomicAdd(&g_denom[d * 2 + (lane >> 4)], alpha);
    float4 o = make_float4(alpha * (v0.x + e0.x), alpha * (v0.y + e0.y),
                           alpha * (v1.x + e1.x), alpha * (v1.y + e1.y));
    float* dptr = &out[(size_t)d * 128 + lane * 4];
    asm volatile("red.global.add.v4.f32 [%0], {%1,%2,%3,%4};"
                 :: "l"(dptr), "f"(o.x), "f"(o.y), "f"(o.z), "f"(o.w) : "memory");
}

// ---------------- finalize: out = out/denom + skip --------------------------
__global__ void k_final(float* __restrict__ out) {
    int i = blockIdx.x * 256 + threadIdx.x;
    if (i >= KN * 32) return;
    int node = i >> 5;
    int j4 = (i & 31) * 4;
    int h = j4 >> 6;
    float den = g_denom[node * 2 + h];
    float inv = den > 0.f ? 1.f / den : 0.f;
    float4 u = *(float4*)&out[(size_t)node * 128 + j4];
    uint2 sku = *(const uint2*)&g_yh[(size_t)node * 512 + 384 + j4];
    float2 s0 = uph2(sku.x), s1 = uph2(sku.y);
    u.x = u.x * inv + s0.x;
    u.y = u.y * inv + s0.y;
    u.z = u.z * inv + s1.x;
    u.w = u.w * inv + s1.y;
    *(float4*)&out[(size_t)node * 128 + j4] = u;
}

// ---------------- launch -----------------------------------------------------
#define NODE_SMEM (65536 + 8192)
#define EDGE_SMEM (65536 + 8192)

extern "C" void kernel_launch(void* const* d_in, const int* in_sizes, int n_in,
                              void* d_out, int out_size) {
    (void)in_sizes; (void)n_in; (void)out_size;
    const int*   n_id    = (const int*)d_in[0];
    const int*   eib     = (const int*)d_in[1];   // [2, M]: src then dst
    const int*   e_id    = (const int*)d_in[2];
    const float* nfeat   = (const float*)d_in[4];
    const float* eraw    = (const float*)d_in[5];
    const float* edge_t  = (const float*)d_in[6];
    const float* memv    = (const float*)d_in[7];
    const float* last_up = (const float*)d_in[8];
    const float* w_t     = (const float*)d_in[9];
    const float* b_t     = (const float*)d_in[10];
    const float* Wq = (const float*)d_in[11];
    const float* Wk = (const float*)d_in[13];
    const float* Wv = (const float*)d_in[15];
    const float* We = (const float*)d_in[17];
    const float* Wskip = (const float*)d_in[18];
    NodeB pb;
    pb.b[0] = (const float*)d_in[12];
    pb.b[1] = (const float*)d_in[14];
    pb.b[2] = (const float*)d_in[16];
    pb.b[3] = (const float*)d_in[19];
    float* out = (float*)d_out;

    cudaFuncSetAttribute(k_node_fused, cudaFuncAttributeMaxDynamicSharedMemorySize, NODE_SMEM);
    cudaFuncSetAttribute(k_edge_gemm, cudaFuncAttributeMaxDynamicSharedMemorySize, EDGE_SMEM);

    k_prep<<<(5 * 32768 + 255) / 256, 256>>>(Wq, Wk, Wv, Wskip, We);
    k_tab<<<(NT * 128 + 255) / 256, 256>>>(w_t, b_t);
    k_init<<<(KN * 128 + 255) / 256, 256>>>(out, last_up, n_id);
    k_node_fused<<<(KN + 127) / 128, 256, NODE_SMEM>>>(n_id, memv, nfeat, pb);
    k_edge_gemm<<<(ME + 127) / 128, 256, EDGE_SMEM>>>(eib, e_id, edge_t, eraw);
    k_attn<<<ME / 8, 256>>>(eib, eib + ME, out);
    k_final<<<(KN * 32 + 255) / 256, 256>>>(out);
}

// round 14
// speedup vs baseline: 1.0751x; 1.0000x over previous
#include <cuda_runtime.h>
#include <cuda_fp16.h>
#include <cstdint>

#define KN 100000   // batch nodes
#define ME 600000   // edges
#define NT 32768    // time-encoding table samples
#define TLO (-1024.0f)
#define TSTEP 0.0625f
#define TINV 16.0f  // 1/step

// ---------------- scratch (device globals) ----------------------------------
__device__ __half g_yh[(size_t)KN * 512];      // per node: [q | k | v | skip] x128
__device__ __half g_eh[(size_t)ME * 128];      // per edge: e = edge_attr @ We
__device__ __half g_wT[(size_t)5 * 128 * 256]; // transposed fp16 weights [mat][n][k]
__device__ __half g_tab[(size_t)NT * 128];     // cos(s_i * w_k + b_k)  (k-indexed)
__device__ float g_lu[KN];
__device__ float g_denom[KN * 2];

// ---------------- helpers ---------------------------------------------------
__device__ __forceinline__ float poly_cos(float x) {
    float n = rintf(x * 0.3183098861837907f);
    float r = fmaf(n, -3.14159274101257f, x);
    r = fmaf(n, 8.742277657347586e-8f, r);
    float r2 = r * r;
    float p = fmaf(r2, -2.7557319e-7f, 2.4801587e-5f);
    p = fmaf(p, r2, -1.3888889e-3f);
    p = fmaf(p, r2, 4.1666668e-2f);
    p = fmaf(p, r2, -0.5f);
    p = fmaf(p, r2, 1.0f);
    int ni = (int)n;
    return (ni & 1) ? -p : p;
}
__device__ __forceinline__ void mma_f16(float* c, const unsigned* a, const unsigned* b) {
    asm volatile("mma.sync.aligned.m16n8k16.row.col.f32.f16.f16.f32 "
                 "{%0,%1,%2,%3}, {%4,%5,%6,%7}, {%8,%9}, {%0,%1,%2,%3};"
                 : "+f"(c[0]), "+f"(c[1]), "+f"(c[2]), "+f"(c[3])
                 : "r"(a[0]), "r"(a[1]), "r"(a[2]), "r"(a[3]), "r"(b[0]), "r"(b[1]));
}
__device__ __forceinline__ void ldsm_x4(unsigned& r0, unsigned& r1, unsigned& r2, unsigned& r3,
                                        uint32_t addr) {
    asm volatile("ldmatrix.sync.aligned.m8n8.x4.shared.b16 {%0,%1,%2,%3}, [%4];"
                 : "=r"(r0), "=r"(r1), "=r"(r2), "=r"(r3) : "r"(addr));
}
__device__ __forceinline__ unsigned pkh2(float a, float b) {
    half2 h = __floats2half2_rn(a, b);
    return *(unsigned*)&h;
}
__device__ __forceinline__ float2 uph2(unsigned u) {
    return __half22float2(*(half2*)&u);
}
__device__ __forceinline__ uint32_t smem_u32(const void* p) {
    uint32_t a;
    asm("{ .reg .u64 t; cvta.to.shared.u64 t, %1; cvt.u32.u64 %0, t; }" : "=r"(a) : "l"(p));
    return a;
}

// ---------------- prep: transpose+convert weights to fp16 -------------------
__global__ void k_prep(const float* __restrict__ W0, const float* __restrict__ W1,
                       const float* __restrict__ W2, const float* __restrict__ W3,
                       const float* __restrict__ W4) {
    int i = blockIdx.x * 256 + threadIdx.x;
    if (i >= 5 * 32768) return;
    int mat = i >> 15, rem = i & 32767;
    int k = rem >> 7, n = rem & 127;
    const float* src = (mat == 0) ? W0 : (mat == 1) ? W1 : (mat == 2) ? W2 : (mat == 3) ? W3 : W4;
    g_wT[((size_t)mat * 128 + n) * 256 + k] = __float2half_rn(src[rem]);
}

// ---------------- table: g_tab[i][k] = cos(s_i * w_k + b_k) -----------------
__global__ void k_tab(const float* __restrict__ w_t, const float* __restrict__ b_t) {
    int i = blockIdx.x * 256 + threadIdx.x;
    if (i >= NT * 128) return;
    int row = i >> 7, k = i & 127;
    float s = TLO + (float)row * TSTEP;
    g_tab[i] = __float2half_rn(poly_cos(fmaf(s, w_t[k], b_t[k])));
}

// ---------------- init: zero out/denom, gather last_update ------------------
__global__ void k_init(float* __restrict__ out,
                       const float* __restrict__ last_update,
                       const int* __restrict__ n_id) {
    int i = blockIdx.x * 256 + threadIdx.x;
    if (i < KN * 128) out[i] = 0.f;
    if (i < KN * 2) g_denom[i] = 0.f;
    if (i < KN) g_lu[i] = last_update[n_id[i]];
}

// ============================================================================
// fp16 GEMM core, 64x64 warp tile: per k16, 4 A-ldsm + 4 B-ldsm feed 32 HMMA.
// Tile layout: [kh(2)][row(128)][8 halves] => kh stride 2048B, ktile 4096B.
// 4 warps per block: wm = warp&1 (m), wn = warp>>1 (n).
// ============================================================================
__device__ __forceinline__ void gemm64(uint32_t As, uint32_t Bs,
                                       int row_base, int col_base,
                                       int lane, float c[4][8][4]) {
    unsigned a[4][4], b[8][2];
    uint32_t l7 = lane & 7;
    uint32_t arow = (uint32_t)(row_base + ((lane >> 3) & 1) * 8 + l7);
    uint32_t abase = As + ((uint32_t)(lane >> 4)) * 2048u + arow * 16u;
#pragma unroll
    for (int mt = 0; mt < 4; mt++)
        ldsm_x4(a[mt][0], a[mt][1], a[mt][2], a[mt][3], abase + (uint32_t)mt * 256u);
    uint32_t bbase = Bs + (uint32_t)(col_base + (lane >> 3) * 8 + l7) * 16u;
    ldsm_x4(b[0][0], b[1][0], b[2][0], b[3][0], bbase);
    ldsm_x4(b[4][0], b[5][0], b[6][0], b[7][0], bbase + 512u);
    ldsm_x4(b[0][1], b[1][1], b[2][1], b[3][1], bbase + 2048u);
    ldsm_x4(b[4][1], b[5][1], b[6][1], b[7][1], bbase + 512u + 2048u);
#pragma unroll
    for (int mt = 0; mt < 4; mt++)
#pragma unroll
        for (int nt = 0; nt < 8; nt++) mma_f16(c[mt][nt], a[mt], b[nt]);
}

// ---------------- fused node GEMM: 4 weight matrices, A smem-resident -------
struct NodeB { const float* b[4]; };

__global__ __launch_bounds__(128, 2) void k_node_fused(const int* __restrict__ n_id,
                                                       const float* __restrict__ memv,
                                                       const float* __restrict__ feat,
                                                       NodeB pb) {
    extern __shared__ __align__(16) char dsm[];
    __half* Asm = (__half*)dsm;                    // 16 ktiles x 4KB = 64KB
    __half* Bsm = (__half*)(dsm + 65536);          // 2 x 4KB double buffer
    __shared__ int nid_s[128];
    const int m0 = blockIdx.x * 128;
    const int tid = threadIdx.x;
    int rows = KN - m0; if (rows > 128) rows = 128;
    nid_s[tid] = n_id[m0 + (tid < rows ? tid : rows - 1)];
    __syncthreads();

    const int warp = tid >> 5, lane = tid & 31;
    const int row_base = (warp & 1) * 64, col_base = (warp >> 1) * 64;
    const int lr = lane >> 2, lc = lane & 3;

    // Phase 1: gather + convert A once (row = tid), resident for all 4 matrices
    {
        const int nid_a = nid_s[tid];
        const float* arow_mem = &memv[(size_t)nid_a * 128];
        const float* arow_feat = &feat[(size_t)nid_a * 128];
#pragma unroll
        for (int kt = 0; kt < 16; kt++) {
            int c0 = kt * 16;
            const float* src = (c0 < 128) ? (arow_mem + c0) : (arow_feat + c0 - 128);
            float4 v0 = *(const float4*)src;
            float4 v1 = *(const float4*)(src + 4);
            float4 v2 = *(const float4*)(src + 8);
            float4 v3 = *(const float4*)(src + 12);
            uint4 p0, p1;
            p0.x = pkh2(v0.x, v0.y); p0.y = pkh2(v0.z, v0.w);
            p0.z = pkh2(v1.x, v1.y); p0.w = pkh2(v1.z, v1.w);
            p1.x = pkh2(v2.x, v2.y); p1.y = pkh2(v2.z, v2.w);
            p1.z = pkh2(v3.x, v3.y); p1.w = pkh2(v3.z, v3.w);
            *(uint4*)&Asm[(size_t)kt * 2048 + tid * 8] = p0;          // kh0 plane
            *(uint4*)&Asm[(size_t)kt * 2048 + 1024 + tid * 8] = p1;   // kh1 plane
        }
    }

    uint32_t as0 = smem_u32(Asm), bs0 = smem_u32(Bsm);
    float c[4][8][4];
#pragma unroll
    for (int mt = 0; mt < 4; mt++)
#pragma unroll
        for (int nt = 0; nt < 8; nt++)
#pragma unroll
            for (int i = 0; i < 4; i++) c[mt][nt][i] = 0.f;

    uint4 bpre0, bpre1;
    auto load_b = [&](int step) {
        int wt = step >> 4, kt = step & 15;
        const __half* src = &g_wT[(size_t)wt * 32768 + (size_t)tid * 256 + kt * 16];
        bpre0 = *(const uint4*)src;
        bpre1 = *(const uint4*)(src + 8);
    };
    auto store_b = [&](int buf) {
        *(uint4*)&Bsm[(size_t)buf * 2048 + tid * 8] = bpre0;
        *(uint4*)&Bsm[(size_t)buf * 2048 + 1024 + tid * 8] = bpre1;
    };

    load_b(0);
    store_b(0);
    __syncthreads();   // also covers Phase-1 A stores

    for (int wt = 0; wt < 4; wt++) {
        for (int kt = 0; kt < 16; kt++) {
            int step = wt * 16 + kt;
            int buf = step & 1;
            if (step < 63) load_b(step + 1);
            gemm64(as0 + (uint32_t)kt * 4096u, bs0 + (uint32_t)buf * 4096u,
                   row_base, col_base, lane, c);
            if (step < 63) { store_b(buf ^ 1); __syncthreads(); }
        }
        const float* bias = pb.b[wt];
#pragma unroll
        for (int nt = 0; nt < 8; nt++) {
            int col = col_base + nt * 8 + lc * 2;
            float2 bb = *(const float2*)&bias[col];
#pragma unroll
            for (int mt = 0; mt < 4; mt++) {
                int r0 = row_base + mt * 16 + lr;
                if (r0 < rows)
                    *(unsigned*)&g_yh[(size_t)(m0 + r0) * 512 + wt * 128 + col] =
                        pkh2(c[mt][nt][0] + bb.x, c[mt][nt][1] + bb.y);
                if (r0 + 8 < rows)
                    *(unsigned*)&g_yh[(size_t)(m0 + r0 + 8) * 512 + wt * 128 + col] =
                        pkh2(c[mt][nt][2] + bb.x, c[mt][nt][3] + bb.y);
                c[mt][nt][0] = 0.f; c[mt][nt][1] = 0.f; c[mt][nt][2] = 0.f; c[mt][nt][3] = 0.f;
            }
        }
    }
}

// ---------------- edge GEMM: B (We) SMEM-resident, A streamed ---------------
__global__ __launch_bounds__(128, 2) void k_edge_gemm(const int* __restrict__ src_a,
                                                      const int* __restrict__ e_id,
                                                      const float* __restrict__ edge_t,
                                                      const float* __restrict__ eraw) {
    extern __shared__ __align__(16) char dsm[];
    __half* Bsm = (__half*)dsm;                    // 16 ktiles x 4KB = 64KB (resident)
    __half* Asm = (__half*)(dsm + 65536);          // 2 x 4KB double buffer
    __shared__ int eid_s[128];
    __shared__ float relt_s[128];
    const int m0 = blockIdx.x * 128;
    const int tid = threadIdx.x;
    int rows = ME - m0; if (rows > 128) rows = 128;
    {
        int r = (tid < rows ? tid : rows - 1);
        int e = e_id[m0 + r];
        eid_s[tid] = e;
        relt_s[tid] = edge_t[e] - g_lu[src_a[m0 + r]];
    }

    const int warp = tid >> 5, lane = tid & 31;
    const int row_base = (warp & 1) * 64, col_base = (warp >> 1) * 64;
    const int lr = lane >> 2, lc = lane & 3;

    // Load B (We) resident: n-row = tid, 16 ktiles
    {
        const __half* brow = &g_wT[(size_t)4 * 32768 + (size_t)tid * 256];
#pragma unroll
        for (int kt = 0; kt < 16; kt++) {
            const __half* src = brow + kt * 16;
            *(uint4*)&Bsm[(size_t)kt * 2048 + tid * 8] = *(const uint4*)src;
            *(uint4*)&Bsm[(size_t)kt * 2048 + 1024 + tid * 8] = *(const uint4*)(src + 8);
        }
    }
    __syncthreads();

    float c[4][8][4];
#pragma unroll
    for (int mt = 0; mt < 4; mt++)
#pragma unroll
        for (int nt = 0; nt < 8; nt++)
#pragma unroll
            for (int i = 0; i < 4; i++) c[mt][nt][i] = 0.f;

    float x = (relt_s[tid] - TLO) * TINV;
    x = fminf(fmaxf(x, 0.0f), (float)(NT - 1) - 1e-3f);
    const int ti = (int)x;
    const float tf = x - (float)ti;
    const __half* trow0 = &g_tab[(size_t)ti * 128];
    const float* arow_msg = &eraw[(size_t)eid_s[tid] * 128];
    uint32_t as0 = smem_u32(Asm), bs0 = smem_u32(Bsm);

    float apre[16];
    auto load_a = [&](int ch, float* ap) {
        int c0 = ch * 16;
        if (c0 < 128) {
            uint4 u0 = *(const uint4*)(trow0 + c0);
            uint4 u1 = *(const uint4*)(trow0 + c0 + 8);
            uint4 w0 = *(const uint4*)(trow0 + 128 + c0);
            uint4 w1 = *(const uint4*)(trow0 + 128 + c0 + 8);
            const unsigned* ua = (const unsigned*)&u0;
            const unsigned* ub = (const unsigned*)&w0;
#pragma unroll
            for (int j = 0; j < 4; j++) {
                float2 lo = uph2(ua[j]), hi = uph2(ub[j]);
                ap[j * 2 + 0] = fmaf(tf, hi.x - lo.x, lo.x);
                ap[j * 2 + 1] = fmaf(tf, hi.y - lo.y, lo.y);
            }
            const unsigned* uc = (const unsigned*)&u1;
            const unsigned* ud = (const unsigned*)&w1;
#pragma unroll
            for (int j = 0; j < 4; j++) {
                float2 lo = uph2(uc[j]), hi = uph2(ud[j]);
                ap[8 + j * 2 + 0] = fmaf(tf, hi.x - lo.x, lo.x);
                ap[8 + j * 2 + 1] = fmaf(tf, hi.y - lo.y, lo.y);
            }
        } else {
            const float* src = arow_msg + (c0 - 128);
            float4 v0 = *(const float4*)src;
            float4 v1 = *(const float4*)(src + 4);
            float4 v2 = *(const float4*)(src + 8);
            float4 v3 = *(const float4*)(src + 12);
            ap[0] = v0.x; ap[1] = v0.y; ap[2] = v0.z; ap[3] = v0.w;
            ap[4] = v1.x; ap[5] = v1.y; ap[6] = v1.z; ap[7] = v1.w;
            ap[8] = v2.x; ap[9] = v2.y; ap[10] = v2.z; ap[11] = v2.w;
            ap[12] = v3.x; ap[13] = v3.y; ap[14] = v3.z; ap[15] = v3.w;
        }
    };
    auto store_a = [&](int buf, const float* ap) {
        uint4 p0, p1;
        p0.x = pkh2(ap[0], ap[1]); p0.y = pkh2(ap[2], ap[3]);
        p0.z = pkh2(ap[4], ap[5]); p0.w = pkh2(ap[6], ap[7]);
        p1.x = pkh2(ap[8], ap[9]); p1.y = pkh2(ap[10], ap[11]);
        p1.z = pkh2(ap[12], ap[13]); p1.w = pkh2(ap[14], ap[15]);
        *(uint4*)&Asm[(size_t)buf * 2048 + tid * 8] = p0;
        *(uint4*)&Asm[(size_t)buf * 2048 + 1024 + tid * 8] = p1;
    };

    load_a(0, apre);
    store_a(0, apre);
    __syncthreads();
    for (int ch = 0; ch < 16; ch++) {
        int buf = ch & 1;
        if (ch < 15) load_a(ch + 1, apre);
        gemm64(as0 + (uint32_t)buf * 4096u, bs0 + (uint32_t)ch * 4096u,
               row_base, col_base, lane, c);
        if (ch < 15) { store_a(buf ^ 1, apre); __syncthreads(); }
    }

#pragma unroll
    for (int nt = 0; nt < 8; nt++) {
        int col = col_base + nt * 8 + lc * 2;
#pragma unroll
        for (int mt = 0; mt < 4; mt++) {
            int r0 = row_base + mt * 16 + lr;
            if (r0 < rows)
                *(unsigned*)&g_eh[(size_t)(m0 + r0) * 128 + col] =
                    pkh2(c[mt][nt][0], c[mt][nt][1]);
            if (r0 + 8 < rows)
                *(unsigned*)&g_eh[(size_t)(m0 + r0 + 8) * 128 + col] =
                    pkh2(c[mt][nt][2], c[mt][nt][3]);
        }
    }
}

// ---------------- fused attention (fp16 inputs, fp32 math/accum) ------------
__global__ __launch_bounds__(256) void k_attn(const int* __restrict__ src_a,
                                              const int* __restrict__ dst_a,
                                              float* __restrict__ out) {
    int gw = (blockIdx.x * 256 + threadIdx.x) >> 5;
    int lane = threadIdx.x & 31;
    if (gw >= ME) return;
    int s = src_a[gw], d = dst_a[gw];
    uint2 qu = *(const uint2*)&g_yh[(size_t)d * 512 + lane * 4];
    uint2 ku = *(const uint2*)&g_yh[(size_t)s * 512 + 128 + lane * 4];
    uint2 vu = *(const uint2*)&g_yh[(size_t)s * 512 + 256 + lane * 4];
    uint2 eu = *(const uint2*)&g_eh[(size_t)gw * 128 + lane * 4];
    float2 q0 = uph2(qu.x), q1 = uph2(qu.y);
    float2 k0 = uph2(ku.x), k1 = uph2(ku.y);
    float2 v0 = uph2(vu.x), v1 = uph2(vu.y);
    float2 e0 = uph2(eu.x), e1 = uph2(eu.y);
    float ke0x = k0.x + e0.x, ke0y = k0.y + e0.y, ke1x = k1.x + e1.x, ke1y = k1.y + e1.y;
    float p = q0.x * ke0x + q0.y * ke0y + q1.x * ke1x + q1.y * ke1y;
    p += __shfl_xor_sync(0xffffffffu, p, 8);
    p += __shfl_xor_sync(0xffffffffu, p, 4);
    p += __shfl_xor_sync(0xffffffffu, p, 2);
    p += __shfl_xor_sync(0xffffffffu, p, 1);
    float alpha = __expf(p * 0.125f);   // 1/sqrt(64)
    if ((lane & 15) == 0) atomicAdd(&g_denom[d * 2 + (lane >> 4)], alpha);
    float4 o = make_float4(alpha * (v0.x + e0.x), alpha * (v0.y + e0.y),
                           alpha * (v1.x + e1.x), alpha * (v1.y + e1.y));
    float* dptr = &out[(size_t)d * 128 + lane * 4];
    asm volatile("red.global.add.v4.f32 [%0], {%1,%2,%3,%4};"
                 :: "l"(dptr), "f"(o.x), "f"(o.y), "f"(o.z), "f"(o.w) : "memory");
}

// ---------------- finalize: out = out/denom + skip --------------------------
__global__ void k_final(float* __restrict__ out) {
    int i = blockIdx.x * 256 + threadIdx.x;
    if (i >= KN * 32) return;
    int node = i >> 5;
    int j4 = (i & 31) * 4;
    int h = j4 >> 6;
    float den = g_denom[node * 2 + h];
    float inv = den > 0.f ? 1.f / den : 0.f;
    float4 u = *(float4*)&out[(size_t)node * 128 + j4];
    uint2 sku = *(const uint2*)&g_yh[(size_t)node * 512 + 384 + j4];
    float2 s0 = uph2(sku.x), s1 = uph2(sku.y);
    u.x = u.x * inv + s0.x;
    u.y = u.y * inv + s0.y;
    u.z = u.z * inv + s1.x;
    u.w = u.w * inv + s1.y;
    *(float4*)&out[(size_t)node * 128 + j4] = u;
}

// ---------------- launch -----------------------------------------------------
#define NODE_SMEM (65536 + 8192)
#define EDGE_SMEM (65536 + 8192)

extern "C" void kernel_launch(void* const* d_in, const int* in_sizes, int n_in,
                              void* d_out, int out_size) {
    (void)in_sizes; (void)n_in; (void)out_size;
    const int*   n_id    = (const int*)d_in[0];
    const int*   eib     = (const int*)d_in[1];   // [2, M]: src then dst
    const int*   e_id    = (const int*)d_in[2];
    const float* nfeat   = (const float*)d_in[4];
    const float* eraw    = (const float*)d_in[5];
    const float* edge_t  = (const float*)d_in[6];
    const float* memv    = (const float*)d_in[7];
    const float* last_up = (const float*)d_in[8];
    const float* w_t     = (const float*)d_in[9];
    const float* b_t     = (const float*)d_in[10];
    const float* Wq = (const float*)d_in[11];
    const float* Wk = (const float*)d_in[13];
    const float* Wv = (const float*)d_in[15];
    const float* We = (const float*)d_in[17];
    const float* Wskip = (const float*)d_in[18];
    NodeB pb;
    pb.b[0] = (const float*)d_in[12];
    pb.b[1] = (const float*)d_in[14];
    pb.b[2] = (const float*)d_in[16];
    pb.b[3] = (const float*)d_in[19];
    float* out = (float*)d_out;

    cudaFuncSetAttribute(k_node_fused, cudaFuncAttributeMaxDynamicSharedMemorySize, NODE_SMEM);
    cudaFuncSetAttribute(k_edge_gemm, cudaFuncAttributeMaxDynamicSharedMemorySize, EDGE_SMEM);

    k_prep<<<(5 * 32768 + 255) / 256, 256>>>(Wq, Wk, Wv, Wskip, We);
    k_tab<<<(NT * 128 + 255) / 256, 256>>>(w_t, b_t);
    k_init<<<(KN * 128 + 255) / 256, 256>>>(out, last_up, n_id);
    k_node_fused<<<(KN + 127) / 128, 128, NODE_SMEM>>>(n_id, memv, nfeat, pb);
    k_edge_gemm<<<(ME + 127) / 128, 128, EDGE_SMEM>>>(eib, e_id, edge_t, eraw);
    k_attn<<<ME / 8, 256>>>(eib, eib + ME, out);
    k_final<<<(KN * 32 + 255) / 256, 256>>>(out);
}

// round 15
// speedup vs baseline: 1.1104x; 1.0329x over previous
#include <cuda_runtime.h>
#include <cuda_fp16.h>
#include <cstdint>

#define KN 100000   // batch nodes
#define ME 600000   // edges
#define NT 32768    // time-encoding table samples
#define TLO (-1024.0f)
#define TSTEP 0.0625f
#define TINV 16.0f  // 1/step

// ---------------- scratch (device globals) ----------------------------------
__device__ __half g_yh[(size_t)KN * 512];      // per node: [q | k | v | skip] x128
__device__ __half g_eh[(size_t)ME * 128];      // per edge: e = edge_attr @ We
__device__ __half g_wT[(size_t)5 * 128 * 256]; // transposed fp16 weights [mat][n][k]
__device__ __half g_tab[(size_t)NT * 128];     // cos(s_i * w_k + b_k)  (k-indexed)
__device__ __half g_tab2[(size_t)NT * 128];    // g(s_i) = cos_row @ We_top (n-indexed)
__device__ float g_lu[KN];
__device__ float g_denom[KN * 2];

// ---------------- helpers ---------------------------------------------------
__device__ __forceinline__ float poly_cos(float x) {
    float n = rintf(x * 0.3183098861837907f);
    float r = fmaf(n, -3.14159274101257f, x);
    r = fmaf(n, 8.742277657347586e-8f, r);
    float r2 = r * r;
    float p = fmaf(r2, -2.7557319e-7f, 2.4801587e-5f);
    p = fmaf(p, r2, -1.3888889e-3f);
    p = fmaf(p, r2, 4.1666668e-2f);
    p = fmaf(p, r2, -0.5f);
    p = fmaf(p, r2, 1.0f);
    int ni = (int)n;
    return (ni & 1) ? -p : p;
}
__device__ __forceinline__ void mma_f16(float* c, const unsigned* a, const unsigned* b) {
    asm volatile("mma.sync.aligned.m16n8k16.row.col.f32.f16.f16.f32 "
                 "{%0,%1,%2,%3}, {%4,%5,%6,%7}, {%8,%9}, {%0,%1,%2,%3};"
                 : "+f"(c[0]), "+f"(c[1]), "+f"(c[2]), "+f"(c[3])
                 : "r"(a[0]), "r"(a[1]), "r"(a[2]), "r"(a[3]), "r"(b[0]), "r"(b[1]));
}
__device__ __forceinline__ void ldsm_x4(unsigned& r0, unsigned& r1, unsigned& r2, unsigned& r3,
                                        uint32_t addr) {
    asm volatile("ldmatrix.sync.aligned.m8n8.x4.shared.b16 {%0,%1,%2,%3}, [%4];"
                 : "=r"(r0), "=r"(r1), "=r"(r2), "=r"(r3) : "r"(addr));
}
__device__ __forceinline__ unsigned pkh2(float a, float b) {
    half2 h = __floats2half2_rn(a, b);
    return *(unsigned*)&h;
}
__device__ __forceinline__ float2 uph2(unsigned u) {
    return __half22float2(*(half2*)&u);
}
__device__ __forceinline__ uint32_t smem_u32(const void* p) {
    uint32_t a;
    asm("{ .reg .u64 t; cvta.to.shared.u64 t, %1; cvt.u32.u64 %0, t; }" : "=r"(a) : "l"(p));
    return a;
}

// ---------------- prep: transpose+convert weights to fp16 -------------------
__global__ void k_prep(const float* __restrict__ W0, const float* __restrict__ W1,
                       const float* __restrict__ W2, const float* __restrict__ W3,
                       const float* __restrict__ W4) {
    int i = blockIdx.x * 256 + threadIdx.x;
    if (i >= 5 * 32768) return;
    int mat = i >> 15, rem = i & 32767;
    int k = rem >> 7, n = rem & 127;
    const float* src = (mat == 0) ? W0 : (mat == 1) ? W1 : (mat == 2) ? W2 : (mat == 3) ? W3 : W4;
    g_wT[((size_t)mat * 128 + n) * 256 + k] = __float2half_rn(src[rem]);
}

// ---------------- table: g_tab[i][k] = cos(s_i * w_k + b_k) -----------------
__global__ void k_tab(const float* __restrict__ w_t, const float* __restrict__ b_t) {
    int i = blockIdx.x * 256 + threadIdx.x;
    if (i >= NT * 128) return;
    int row = i >> 7, k = i & 127;
    float s = TLO + (float)row * TSTEP;
    g_tab[i] = __float2half_rn(poly_cos(fmaf(s, w_t[k], b_t[k])));
}

// ---------------- init: zero out/denom, gather last_update ------------------
__global__ void k_init(float* __restrict__ out,
                       const float* __restrict__ last_update,
                       const int* __restrict__ n_id) {
    int i = blockIdx.x * 256 + threadIdx.x;
    if (i < KN * 128) out[i] = 0.f;
    if (i < KN * 2) g_denom[i] = 0.f;
    if (i < KN) g_lu[i] = last_update[n_id[i]];
}

// ============================================================================
// fp16 GEMM core, 64x64 warp tile. Tile: [kh(2)][row(128)][8 halves], ktile 4KB.
// ============================================================================
__device__ __forceinline__ void gemm64(uint32_t As, uint32_t Bs,
                                       int row_base, int col_base,
                                       int lane, float c[4][8][4]) {
    unsigned a[4][4], b[8][2];
    uint32_t l7 = lane & 7;
    uint32_t arow = (uint32_t)(row_base + ((lane >> 3) & 1) * 8 + l7);
    uint32_t abase = As + ((uint32_t)(lane >> 4)) * 2048u + arow * 16u;
#pragma unroll
    for (int mt = 0; mt < 4; mt++)
        ldsm_x4(a[mt][0], a[mt][1], a[mt][2], a[mt][3], abase + (uint32_t)mt * 256u);
    uint32_t bbase = Bs + (uint32_t)(col_base + (lane >> 3) * 8 + l7) * 16u;
    ldsm_x4(b[0][0], b[1][0], b[2][0], b[3][0], bbase);
    ldsm_x4(b[4][0], b[5][0], b[6][0], b[7][0], bbase + 512u);
    ldsm_x4(b[0][1], b[1][1], b[2][1], b[3][1], bbase + 2048u);
    ldsm_x4(b[4][1], b[5][1], b[6][1], b[7][1], bbase + 512u + 2048u);
#pragma unroll
    for (int mt = 0; mt < 4; mt++)
#pragma unroll
        for (int nt = 0; nt < 8; nt++) mma_f16(c[mt][nt], a[mt], b[nt]);
}

// ---------------- g table GEMM: g_tab2 = g_tab @ We_top ---------------------
__global__ __launch_bounds__(128, 2) void k_tabg() {
    extern __shared__ __align__(16) char dsm[];
    __half* Bsm = (__half*)dsm;                    // 8 ktiles x 4KB = 32KB (We_top)
    __half* Asm = (__half*)(dsm + 32768);          // 2 x 4KB
    const int m0 = blockIdx.x * 128;
    const int tid = threadIdx.x;
    const int warp = tid >> 5, lane = tid & 31;
    const int row_base = (warp & 1) * 64, col_base = (warp >> 1) * 64;
    const int lr = lane >> 2, lc = lane & 3;

    {
        const __half* brow = &g_wT[(size_t)4 * 32768 + (size_t)tid * 256];
#pragma unroll
        for (int kt = 0; kt < 8; kt++) {
            const __half* src = brow + kt * 16;
            *(uint4*)&Bsm[(size_t)kt * 2048 + tid * 8] = *(const uint4*)src;
            *(uint4*)&Bsm[(size_t)kt * 2048 + 1024 + tid * 8] = *(const uint4*)(src + 8);
        }
    }

    uint32_t as0 = smem_u32(Asm), bs0 = smem_u32(Bsm);
    float c[4][8][4];
#pragma unroll
    for (int mt = 0; mt < 4; mt++)
#pragma unroll
        for (int nt = 0; nt < 8; nt++)
#pragma unroll
            for (int i = 0; i < 4; i++) c[mt][nt][i] = 0.f;

    const __half* arow = &g_tab[(size_t)(m0 + tid) * 128];
    uint4 ap0, ap1;
    auto load_a = [&](int ch) {
        ap0 = *(const uint4*)(arow + ch * 16);
        ap1 = *(const uint4*)(arow + ch * 16 + 8);
    };
    auto store_a = [&](int buf) {
        *(uint4*)&Asm[(size_t)buf * 2048 + tid * 8] = ap0;
        *(uint4*)&Asm[(size_t)buf * 2048 + 1024 + tid * 8] = ap1;
    };

    load_a(0); store_a(0);
    __syncthreads();
    for (int ch = 0; ch < 8; ch++) {
        int buf = ch & 1;
        if (ch < 7) load_a(ch + 1);
        gemm64(as0 + (uint32_t)buf * 4096u, bs0 + (uint32_t)ch * 4096u,
               row_base, col_base, lane, c);
        if (ch < 7) { store_a(buf ^ 1); __syncthreads(); }
    }

#pragma unroll
    for (int nt = 0; nt < 8; nt++) {
        int col = col_base + nt * 8 + lc * 2;
#pragma unroll
        for (int mt = 0; mt < 4; mt++) {
            int r0 = row_base + mt * 16 + lr;
            *(unsigned*)&g_tab2[(size_t)(m0 + r0) * 128 + col] = pkh2(c[mt][nt][0], c[mt][nt][1]);
            *(unsigned*)&g_tab2[(size_t)(m0 + r0 + 8) * 128 + col] = pkh2(c[mt][nt][2], c[mt][nt][3]);
        }
    }
}

// ---------------- fused node GEMM: 4 weight matrices, A smem-resident -------
struct NodeB { const float* b[4]; };

__global__ __launch_bounds__(128, 2) void k_node_fused(const int* __restrict__ n_id,
                                                       const float* __restrict__ memv,
                                                       const float* __restrict__ feat,
                                                       NodeB pb) {
    extern __shared__ __align__(16) char dsm[];
    __half* Asm = (__half*)dsm;                    // 16 ktiles x 4KB = 64KB
    __half* Bsm = (__half*)(dsm + 65536);          // 2 x 4KB double buffer
    __shared__ int nid_s[128];
    const int m0 = blockIdx.x * 128;
    const int tid = threadIdx.x;
    int rows = KN - m0; if (rows > 128) rows = 128;
    nid_s[tid] = n_id[m0 + (tid < rows ? tid : rows - 1)];
    __syncthreads();

    const int warp = tid >> 5, lane = tid & 31;
    const int row_base = (warp & 1) * 64, col_base = (warp >> 1) * 64;
    const int lr = lane >> 2, lc = lane & 3;

    {
        const int nid_a = nid_s[tid];
        const float* arow_mem = &memv[(size_t)nid_a * 128];
        const float* arow_feat = &feat[(size_t)nid_a * 128];
#pragma unroll
        for (int kt = 0; kt < 16; kt++) {
            int c0 = kt * 16;
            const float* src = (c0 < 128) ? (arow_mem + c0) : (arow_feat + c0 - 128);
            float4 v0 = *(const float4*)src;
            float4 v1 = *(const float4*)(src + 4);
            float4 v2 = *(const float4*)(src + 8);
            float4 v3 = *(const float4*)(src + 12);
            uint4 p0, p1;
            p0.x = pkh2(v0.x, v0.y); p0.y = pkh2(v0.z, v0.w);
            p0.z = pkh2(v1.x, v1.y); p0.w = pkh2(v1.z, v1.w);
            p1.x = pkh2(v2.x, v2.y); p1.y = pkh2(v2.z, v2.w);
            p1.z = pkh2(v3.x, v3.y); p1.w = pkh2(v3.z, v3.w);
            *(uint4*)&Asm[(size_t)kt * 2048 + tid * 8] = p0;
            *(uint4*)&Asm[(size_t)kt * 2048 + 1024 + tid * 8] = p1;
        }
    }

    uint32_t as0 = smem_u32(Asm), bs0 = smem_u32(Bsm);
    float c[4][8][4];
#pragma unroll
    for (int mt = 0; mt < 4; mt++)
#pragma unroll
        for (int nt = 0; nt < 8; nt++)
#pragma unroll
            for (int i = 0; i < 4; i++) c[mt][nt][i] = 0.f;

    uint4 bpre0, bpre1;
    auto load_b = [&](int step) {
        int wt = step >> 4, kt = step & 15;
        const __half* src = &g_wT[(size_t)wt * 32768 + (size_t)tid * 256 + kt * 16];
        bpre0 = *(const uint4*)src;
        bpre1 = *(const uint4*)(src + 8);
    };
    auto store_b = [&](int buf) {
        *(uint4*)&Bsm[(size_t)buf * 2048 + tid * 8] = bpre0;
        *(uint4*)&Bsm[(size_t)buf * 2048 + 1024 + tid * 8] = bpre1;
    };

    load_b(0);
    store_b(0);
    __syncthreads();

    for (int wt = 0; wt < 4; wt++) {
        for (int kt = 0; kt < 16; kt++) {
            int step = wt * 16 + kt;
            int buf = step & 1;
            if (step < 63) load_b(step + 1);
            gemm64(as0 + (uint32_t)kt * 4096u, bs0 + (uint32_t)buf * 4096u,
                   row_base, col_base, lane, c);
            if (step < 63) { store_b(buf ^ 1); __syncthreads(); }
        }
        const float* bias = pb.b[wt];
#pragma unroll
        for (int nt = 0; nt < 8; nt++) {
            int col = col_base + nt * 8 + lc * 2;
            float2 bb = *(const float2*)&bias[col];
#pragma unroll
            for (int mt = 0; mt < 4; mt++) {
                int r0 = row_base + mt * 16 + lr;
                if (r0 < rows)
                    *(unsigned*)&g_yh[(size_t)(m0 + r0) * 512 + wt * 128 + col] =
                        pkh2(c[mt][nt][0] + bb.x, c[mt][nt][1] + bb.y);
                if (r0 + 8 < rows)
                    *(unsigned*)&g_yh[(size_t)(m0 + r0 + 8) * 512 + wt * 128 + col] =
                        pkh2(c[mt][nt][2] + bb.x, c[mt][nt][3] + bb.y);
                c[mt][nt][0] = 0.f; c[mt][nt][1] = 0.f; c[mt][nt][2] = 0.f; c[mt][nt][3] = 0.f;
            }
        }
    }
}

// ---------------- edge GEMM: K=128 (msg @ We_bot) + epilogue g(rt) add ------
#define GST 136   // g-stage smem stride in halves

__global__ __launch_bounds__(128, 2) void k_edge_gemm(const int* __restrict__ src_a,
                                                      const int* __restrict__ e_id,
                                                      const float* __restrict__ edge_t,
                                                      const float* __restrict__ eraw) {
    extern __shared__ __align__(16) char dsm[];
    __half* Bsm = (__half*)dsm;                    // 8 ktiles x 4KB = 32KB (We_bot)
    __half* Gsm = (__half*)dsm;                    // overlay after mainloop: 128 x GST halves
    __half* Asm = (__half*)(dsm + 32768);          // 2 x 4KB double buffer
    __shared__ int eid_s[128];
    __shared__ float relt_s[128];
    const int m0 = blockIdx.x * 128;
    const int tid = threadIdx.x;
    int rows = ME - m0; if (rows > 128) rows = 128;
    {
        int r = (tid < rows ? tid : rows - 1);
        int e = e_id[m0 + r];
        eid_s[tid] = e;
        relt_s[tid] = edge_t[e] - g_lu[src_a[m0 + r]];
    }

    const int warp = tid >> 5, lane = tid & 31;
    const int row_base = (warp & 1) * 64, col_base = (warp >> 1) * 64;
    const int lr = lane >> 2, lc = lane & 3;

    // Load B (We_bot, k=128..255) resident: 8 ktiles
    {
        const __half* brow = &g_wT[(size_t)4 * 32768 + (size_t)tid * 256 + 128];
#pragma unroll
        for (int kt = 0; kt < 8; kt++) {
            const __half* src = brow + kt * 16;
            *(uint4*)&Bsm[(size_t)kt * 2048 + tid * 8] = *(const uint4*)src;
            *(uint4*)&Bsm[(size_t)kt * 2048 + 1024 + tid * 8] = *(const uint4*)(src + 8);
        }
    }
    __syncthreads();

    float c[4][8][4];
#pragma unroll
    for (int mt = 0; mt < 4; mt++)
#pragma unroll
        for (int nt = 0; nt < 8; nt++)
#pragma unroll
            for (int i = 0; i < 4; i++) c[mt][nt][i] = 0.f;

    float x = (relt_s[tid] - TLO) * TINV;
    x = fminf(fmaxf(x, 0.0f), (float)(NT - 1) - 1e-3f);
    const int ti = (int)x;
    const float tf = x - (float)ti;
    const float* arow_msg = &eraw[(size_t)eid_s[tid] * 128];
    uint32_t as0 = smem_u32(Asm), bs0 = smem_u32(Bsm);

    float apre[16];
    auto load_a = [&](int ch, float* ap) {
        const float* src = arow_msg + ch * 16;
        float4 v0 = *(const float4*)src;
        float4 v1 = *(const float4*)(src + 4);
        float4 v2 = *(const float4*)(src + 8);
        float4 v3 = *(const float4*)(src + 12);
        ap[0] = v0.x; ap[1] = v0.y; ap[2] = v0.z; ap[3] = v0.w;
        ap[4] = v1.x; ap[5] = v1.y; ap[6] = v1.z; ap[7] = v1.w;
        ap[8] = v2.x; ap[9] = v2.y; ap[10] = v2.z; ap[11] = v2.w;
        ap[12] = v3.x; ap[13] = v3.y; ap[14] = v3.z; ap[15] = v3.w;
    };
    auto store_a = [&](int buf, const float* ap) {
        uint4 p0, p1;
        p0.x = pkh2(ap[0], ap[1]); p0.y = pkh2(ap[2], ap[3]);
        p0.z = pkh2(ap[4], ap[5]); p0.w = pkh2(ap[6], ap[7]);
        p1.x = pkh2(ap[8], ap[9]); p1.y = pkh2(ap[10], ap[11]);
        p1.z = pkh2(ap[12], ap[13]); p1.w = pkh2(ap[14], ap[15]);
        *(uint4*)&Asm[(size_t)buf * 2048 + tid * 8] = p0;
        *(uint4*)&Asm[(size_t)buf * 2048 + 1024 + tid * 8] = p1;
    };

    load_a(0, apre);
    store_a(0, apre);
    __syncthreads();
    for (int ch = 0; ch < 8; ch++) {
        int buf = ch & 1;
        if (ch < 7) load_a(ch + 1, apre);
        gemm64(as0 + (uint32_t)buf * 4096u, bs0 + (uint32_t)ch * 4096u,
               row_base, col_base, lane, c);
        if (ch < 7) { store_a(buf ^ 1, apre); __syncthreads(); }
    }

    // g-stage: lerp g(rt) row for this thread's edge into SMEM (overlay) -----
    __syncthreads();   // Bsm/Asm dead
    {
        const __half* gr0 = &g_tab2[(size_t)ti * 128];
        const __half* gr1 = gr0 + 128;
#pragma unroll
        for (int j = 0; j < 16; j++) {
            uint2 lo = *(const uint2*)(gr0 + j * 8);
            uint2 lo2 = *(const uint2*)(gr0 + j * 8 + 4);
            uint2 hi = *(const uint2*)(gr1 + j * 8);
            uint2 hi2 = *(const uint2*)(gr1 + j * 8 + 4);
            float2 a0 = uph2(lo.x), a1 = uph2(lo.y), a2 = uph2(lo2.x), a3 = uph2(lo2.y);
            float2 b0 = uph2(hi.x), b1 = uph2(hi.y), b2 = uph2(hi2.x), b3 = uph2(hi2.y);
            uint4 o;
            o.x = pkh2(fmaf(tf, b0.x - a0.x, a0.x), fmaf(tf, b0.y - a0.y, a0.y));
            o.y = pkh2(fmaf(tf, b1.x - a1.x, a1.x), fmaf(tf, b1.y - a1.y, a1.y));
            o.z = pkh2(fmaf(tf, b2.x - a2.x, a2.x), fmaf(tf, b2.y - a2.y, a2.y));
            o.w = pkh2(fmaf(tf, b3.x - a3.x, a3.x), fmaf(tf, b3.y - a3.y, a3.y));
            *(uint4*)&Gsm[(size_t)tid * GST + j * 8] = o;
        }
    }
    __syncthreads();

    // epilogue: e = c + g, write g_eh ----------------------------------------
#pragma unroll
    for (int nt = 0; nt < 8; nt++) {
        int col = col_base + nt * 8 + lc * 2;
#pragma unroll
        for (int mt = 0; mt < 4; mt++) {
            int r0 = row_base + mt * 16 + lr;
            if (r0 < rows) {
                float2 gg = uph2(*(unsigned*)&Gsm[(size_t)r0 * GST + col]);
                *(unsigned*)&g_eh[(size_t)(m0 + r0) * 128 + col] =
                    pkh2(c[mt][nt][0] + gg.x, c[mt][nt][1] + gg.y);
            }
            if (r0 + 8 < rows) {
                float2 gg = uph2(*(unsigned*)&Gsm[(size_t)(r0 + 8) * GST + col]);
                *(unsigned*)&g_eh[(size_t)(m0 + r0 + 8) * 128 + col] =
                    pkh2(c[mt][nt][2] + gg.x, c[mt][nt][3] + gg.y);
            }
        }
    }
}

// ---------------- fused attention (fp16 inputs, fp32 math/accum) ------------
__global__ __launch_bounds__(256) void k_attn(const int* __restrict__ src_a,
                                              const int* __restrict__ dst_a,
                                              float* __restrict__ out) {
    int gw = (blockIdx.x * 256 + threadIdx.x) >> 5;
    int lane = threadIdx.x & 31;
    if (gw >= ME) return;
    int s = src_a[gw], d = dst_a[gw];
    uint2 qu = *(const uint2*)&g_yh[(size_t)d * 512 + lane * 4];
    uint2 ku = *(const uint2*)&g_yh[(size_t)s * 512 + 128 + lane * 4];
    uint2 vu = *(const uint2*)&g_yh[(size_t)s * 512 + 256 + lane * 4];
    uint2 eu = *(const uint2*)&g_eh[(size_t)gw * 128 + lane * 4];
    float2 q0 = uph2(qu.x), q1 = uph2(qu.y);
    float2 k0 = uph2(ku.x), k1 = uph2(ku.y);
    float2 v0 = uph2(vu.x), v1 = uph2(vu.y);
    float2 e0 = uph2(eu.x), e1 = uph2(eu.y);
    float ke0x = k0.x + e0.x, ke0y = k0.y + e0.y, ke1x = k1.x + e1.x, ke1y = k1.y + e1.y;
    float p = q0.x * ke0x + q0.y * ke0y + q1.x * ke1x + q1.y * ke1y;
    p += __shfl_xor_sync(0xffffffffu, p, 8);
    p += __shfl_xor_sync(0xffffffffu, p, 4);
    p += __shfl_xor_sync(0xffffffffu, p, 2);
    p += __shfl_xor_sync(0xffffffffu, p, 1);
    float alpha = __expf(p * 0.125f);   // 1/sqrt(64)
    if ((lane & 15) == 0) atomicAdd(&g_denom[d * 2 + (lane >> 4)], alpha);
    float4 o = make_float4(alpha * (v0.x + e0.x), alpha * (v0.y + e0.y),
                           alpha * (v1.x + e1.x), alpha * (v1.y + e1.y));
    float* dptr = &out[(size_t)d * 128 + lane * 4];
    asm volatile("red.global.add.v4.f32 [%0], {%1,%2,%3,%4};"
                 :: "l"(dptr), "f"(o.x), "f"(o.y), "f"(o.z), "f"(o.w) : "memory");
}

// ---------------- finalize: out = out/denom + skip --------------------------
__global__ void k_final(float* __restrict__ out) {
    int i = blockIdx.x * 256 + threadIdx.x;
    if (i >= KN * 32) return;
    int node = i >> 5;
    int j4 = (i & 31) * 4;
    int h = j4 >> 6;
    float den = g_denom[node * 2 + h];
    float inv = den > 0.f ? 1.f / den : 0.f;
    float4 u = *(float4*)&out[(size_t)node * 128 + j4];
    uint2 sku = *(const uint2*)&g_yh[(size_t)node * 512 + 384 + j4];
    float2 s0 = uph2(sku.x), s1 = uph2(sku.y);
    u.x = u.x * inv + s0.x;
    u.y = u.y * inv + s0.y;
    u.z = u.z * inv + s1.x;
    u.w = u.w * inv + s1.y;
    *(float4*)&out[(size_t)node * 128 + j4] = u;
}

// ---------------- launch -----------------------------------------------------
#define NODE_SMEM (65536 + 8192)
#define EDGE_SMEM (32768 + 8192)
#define TABG_SMEM (32768 + 8192)

extern "C" void kernel_launch(void* const* d_in, const int* in_sizes, int n_in,
                              void* d_out, int out_size) {
    (void)in_sizes; (void)n_in; (void)out_size;
    const int*   n_id    = (const int*)d_in[0];
    const int*   eib     = (const int*)d_in[1];   // [2, M]: src then dst
    const int*   e_id    = (const int*)d_in[2];
    const float* nfeat   = (const float*)d_in[4];
    const float* eraw    = (const float*)d_in[5];
    const float* edge_t  = (const float*)d_in[6];
    const float* memv    = (const float*)d_in[7];
    const float* last_up = (const float*)d_in[8];
    const float* w_t     = (const float*)d_in[9];
    const float* b_t     = (const float*)d_in[10];
    const float* Wq = (const float*)d_in[11];
    const float* Wk = (const float*)d_in[13];
    const float* Wv = (const float*)d_in[15];
    const float* We = (const float*)d_in[17];
    const float* Wskip = (const float*)d_in[18];
    NodeB pb;
    pb.b[0] = (const float*)d_in[12];
    pb.b[1] = (const float*)d_in[14];
    pb.b[2] = (const float*)d_in[16];
    pb.b[3] = (const float*)d_in[19];
    float* out = (float*)d_out;

    cudaFuncSetAttribute(k_node_fused, cudaFuncAttributeMaxDynamicSharedMemorySize, NODE_SMEM);
    cudaFuncSetAttribute(k_edge_gemm, cudaFuncAttributeMaxDynamicSharedMemorySize, EDGE_SMEM);
    cudaFuncSetAttribute(k_tabg, cudaFuncAttributeMaxDynamicSharedMemorySize, TABG_SMEM);

    k_prep<<<(5 * 32768 + 255) / 256, 256>>>(Wq, Wk, Wv, Wskip, We);
    k_tab<<<(NT * 128 + 255) / 256, 256>>>(w_t, b_t);
    k_tabg<<<NT / 128, 128, TABG_SMEM>>>();
    k_init<<<(KN * 128 + 255) / 256, 256>>>(out, last_up, n_id);
    k_node_fused<<<(KN + 127) / 128, 128, NODE_SMEM>>>(n_id, memv, nfeat, pb);
    k_edge_gemm<<<(ME + 127) / 128, 128, EDGE_SMEM>>>(eib, e_id, edge_t, eraw);
    k_attn<<<ME / 8, 256>>>(eib, eib + ME, out);
    k_final<<<(KN * 32 + 255) / 256, 256>>>(out);
}

// round 16
// speedup vs baseline: 1.1542x; 1.0394x over previous
#include <cuda_runtime.h>
#include <cuda_fp16.h>
#include <cstdint>

#define KN 100000   // batch nodes
#define ME 600000   // edges
#define NT 32768    // time-encoding table samples
#define TLO (-1024.0f)
#define TSTEP 0.0625f
#define TINV 16.0f  // 1/step

// ---------------- scratch (device globals) ----------------------------------
__device__ __half g_yh[(size_t)KN * 512];      // per node: [q | k | v | skip] x128
__device__ __half g_eh[(size_t)ME * 128];      // per edge: e = edge_attr @ We
__device__ __half g_acc[(size_t)KN * 128];     // attention accumulator (fp16 atomics)
__device__ __half g_wT[(size_t)5 * 128 * 256]; // transposed fp16 weights [mat][n][k]
__device__ __half g_tab[(size_t)NT * 128];     // cos(s_i * w_k + b_k)  (k-indexed)
__device__ __half g_tab2[(size_t)NT * 128];    // g(s_i) = cos_row @ We_top (n-indexed)
__device__ float g_lu[KN];
__device__ float g_denom[KN * 2];

// ---------------- helpers ---------------------------------------------------
__device__ __forceinline__ float poly_cos(float x) {
    float n = rintf(x * 0.3183098861837907f);
    float r = fmaf(n, -3.14159274101257f, x);
    r = fmaf(n, 8.742277657347586e-8f, r);
    float r2 = r * r;
    float p = fmaf(r2, -2.7557319e-7f, 2.4801587e-5f);
    p = fmaf(p, r2, -1.3888889e-3f);
    p = fmaf(p, r2, 4.1666668e-2f);
    p = fmaf(p, r2, -0.5f);
    p = fmaf(p, r2, 1.0f);
    int ni = (int)n;
    return (ni & 1) ? -p : p;
}
__device__ __forceinline__ void mma_f16(float* c, const unsigned* a, const unsigned* b) {
    asm volatile("mma.sync.aligned.m16n8k16.row.col.f32.f16.f16.f32 "
                 "{%0,%1,%2,%3}, {%4,%5,%6,%7}, {%8,%9}, {%0,%1,%2,%3};"
                 : "+f"(c[0]), "+f"(c[1]), "+f"(c[2]), "+f"(c[3])
                 : "r"(a[0]), "r"(a[1]), "r"(a[2]), "r"(a[3]), "r"(b[0]), "r"(b[1]));
}
__device__ __forceinline__ void ldsm_x4(unsigned& r0, unsigned& r1, unsigned& r2, unsigned& r3,
                                        uint32_t addr) {
    asm volatile("ldmatrix.sync.aligned.m8n8.x4.shared.b16 {%0,%1,%2,%3}, [%4];"
                 : "=r"(r0), "=r"(r1), "=r"(r2), "=r"(r3) : "r"(addr));
}
__device__ __forceinline__ unsigned pkh2(float a, float b) {
    half2 h = __floats2half2_rn(a, b);
    return *(unsigned*)&h;
}
__device__ __forceinline__ float2 uph2(unsigned u) {
    return __half22float2(*(half2*)&u);
}
__device__ __forceinline__ uint32_t smem_u32(const void* p) {
    uint32_t a;
    asm("{ .reg .u64 t; cvta.to.shared.u64 t, %1; cvt.u32.u64 %0, t; }" : "=r"(a) : "l"(p));
    return a;
}

// ---------------- prep: transpose+convert weights to fp16 -------------------
__global__ void k_prep(const float* __restrict__ W0, const float* __restrict__ W1,
                       const float* __restrict__ W2, const float* __restrict__ W3,
                       const float* __restrict__ W4) {
    int i = blockIdx.x * 256 + threadIdx.x;
    if (i >= 5 * 32768) return;
    int mat = i >> 15, rem = i & 32767;
    int k = rem >> 7, n = rem & 127;
    const float* src = (mat == 0) ? W0 : (mat == 1) ? W1 : (mat == 2) ? W2 : (mat == 3) ? W3 : W4;
    g_wT[((size_t)mat * 128 + n) * 256 + k] = __float2half_rn(src[rem]);
}

// ---------------- table: g_tab[i][k] = cos(s_i * w_k + b_k) -----------------
__global__ void k_tab(const float* __restrict__ w_t, const float* __restrict__ b_t) {
    int i = blockIdx.x * 256 + threadIdx.x;
    if (i >= NT * 128) return;
    int row = i >> 7, k = i & 127;
    float s = TLO + (float)row * TSTEP;
    g_tab[i] = __float2half_rn(poly_cos(fmaf(s, w_t[k], b_t[k])));
}

// ---------------- init: zero acc/denom, gather last_update ------------------
__global__ void k_init(const float* __restrict__ last_update,
                       const int* __restrict__ n_id) {
    int i = blockIdx.x * 256 + threadIdx.x;
    if (i < KN * 16) ((uint4*)g_acc)[i] = make_uint4(0u, 0u, 0u, 0u);
    if (i < KN * 2) g_denom[i] = 0.f;
    if (i < KN) g_lu[i] = last_update[n_id[i]];
}

// ============================================================================
// fp16 GEMM core, 64x64 warp tile. Tile: [kh(2)][row(128)][8 halves], ktile 4KB.
// ============================================================================
__device__ __forceinline__ void gemm64(uint32_t As, uint32_t Bs,
                                       int row_base, int col_base,
                                       int lane, float c[4][8][4]) {
    unsigned a[4][4], b[8][2];
    uint32_t l7 = lane & 7;
    uint32_t arow = (uint32_t)(row_base + ((lane >> 3) & 1) * 8 + l7);
    uint32_t abase = As + ((uint32_t)(lane >> 4)) * 2048u + arow * 16u;
#pragma unroll
    for (int mt = 0; mt < 4; mt++)
        ldsm_x4(a[mt][0], a[mt][1], a[mt][2], a[mt][3], abase + (uint32_t)mt * 256u);
    uint32_t bbase = Bs + (uint32_t)(col_base + (lane >> 3) * 8 + l7) * 16u;
    ldsm_x4(b[0][0], b[1][0], b[2][0], b[3][0], bbase);
    ldsm_x4(b[4][0], b[5][0], b[6][0], b[7][0], bbase + 512u);
    ldsm_x4(b[0][1], b[1][1], b[2][1], b[3][1], bbase + 2048u);
    ldsm_x4(b[4][1], b[5][1], b[6][1], b[7][1], bbase + 512u + 2048u);
#pragma unroll
    for (int mt = 0; mt < 4; mt++)
#pragma unroll
        for (int nt = 0; nt < 8; nt++) mma_f16(c[mt][nt], a[mt], b[nt]);
}

// ---------------- g table GEMM: g_tab2 = g_tab @ We_top ---------------------
__global__ __launch_bounds__(128, 2) void k_tabg() {
    extern __shared__ __align__(16) char dsm[];
    __half* Bsm = (__half*)dsm;                    // 8 ktiles x 4KB = 32KB (We_top)
    __half* Asm = (__half*)(dsm + 32768);          // 2 x 4KB
    const int m0 = blockIdx.x * 128;
    const int tid = threadIdx.x;
    const int warp = tid >> 5, lane = tid & 31;
    const int row_base = (warp & 1) * 64, col_base = (warp >> 1) * 64;
    const int lr = lane >> 2, lc = lane & 3;

    {
        const __half* brow = &g_wT[(size_t)4 * 32768 + (size_t)tid * 256];
#pragma unroll
        for (int kt = 0; kt < 8; kt++) {
            const __half* src = brow + kt * 16;
            *(uint4*)&Bsm[(size_t)kt * 2048 + tid * 8] = *(const uint4*)src;
            *(uint4*)&Bsm[(size_t)kt * 2048 + 1024 + tid * 8] = *(const uint4*)(src + 8);
        }
    }

    uint32_t as0 = smem_u32(Asm), bs0 = smem_u32(Bsm);
    float c[4][8][4];
#pragma unroll
    for (int mt = 0; mt < 4; mt++)
#pragma unroll
        for (int nt = 0; nt < 8; nt++)
#pragma unroll
            for (int i = 0; i < 4; i++) c[mt][nt][i] = 0.f;

    const __half* arow = &g_tab[(size_t)(m0 + tid) * 128];
    uint4 ap0, ap1;
    auto load_a = [&](int ch) {
        ap0 = *(const uint4*)(arow + ch * 16);
        ap1 = *(const uint4*)(arow + ch * 16 + 8);
    };
    auto store_a = [&](int buf) {
        *(uint4*)&Asm[(size_t)buf * 2048 + tid * 8] = ap0;
        *(uint4*)&Asm[(size_t)buf * 2048 + 1024 + tid * 8] = ap1;
    };

    load_a(0); store_a(0);
    __syncthreads();
    for (int ch = 0; ch < 8; ch++) {
        int buf = ch & 1;
        if (ch < 7) load_a(ch + 1);
        gemm64(as0 + (uint32_t)buf * 4096u, bs0 + (uint32_t)ch * 4096u,
               row_base, col_base, lane, c);
        if (ch < 7) { store_a(buf ^ 1); __syncthreads(); }
    }

#pragma unroll
    for (int nt = 0; nt < 8; nt++) {
        int col = col_base + nt * 8 + lc * 2;
#pragma unroll
        for (int mt = 0; mt < 4; mt++) {
            int r0 = row_base + mt * 16 + lr;
            *(unsigned*)&g_tab2[(size_t)(m0 + r0) * 128 + col] = pkh2(c[mt][nt][0], c[mt][nt][1]);
            *(unsigned*)&g_tab2[(size_t)(m0 + r0 + 8) * 128 + col] = pkh2(c[mt][nt][2], c[mt][nt][3]);
        }
    }
}

// ---------------- fused node GEMM: 4 weight matrices, A smem-resident -------
struct NodeB { const float* b[4]; };

__global__ __launch_bounds__(128, 2) void k_node_fused(const int* __restrict__ n_id,
                                                       const float* __restrict__ memv,
                                                       const float* __restrict__ feat,
                                                       NodeB pb) {
    extern __shared__ __align__(16) char dsm[];
    __half* Asm = (__half*)dsm;                    // 16 ktiles x 4KB = 64KB
    __half* Bsm = (__half*)(dsm + 65536);          // 2 x 4KB double buffer
    __shared__ int nid_s[128];
    const int m0 = blockIdx.x * 128;
    const int tid = threadIdx.x;
    int rows = KN - m0; if (rows > 128) rows = 128;
    nid_s[tid] = n_id[m0 + (tid < rows ? tid : rows - 1)];
    __syncthreads();

    const int warp = tid >> 5, lane = tid & 31;
    const int row_base = (warp & 1) * 64, col_base = (warp >> 1) * 64;
    const int lr = lane >> 2, lc = lane & 3;

    {
        const int nid_a = nid_s[tid];
        const float* arow_mem = &memv[(size_t)nid_a * 128];
        const float* arow_feat = &feat[(size_t)nid_a * 128];
#pragma unroll
        for (int kt = 0; kt < 16; kt++) {
            int c0 = kt * 16;
            const float* src = (c0 < 128) ? (arow_mem + c0) : (arow_feat + c0 - 128);
            float4 v0 = *(const float4*)src;
            float4 v1 = *(const float4*)(src + 4);
            float4 v2 = *(const float4*)(src + 8);
            float4 v3 = *(const float4*)(src + 12);
            uint4 p0, p1;
            p0.x = pkh2(v0.x, v0.y); p0.y = pkh2(v0.z, v0.w);
            p0.z = pkh2(v1.x, v1.y); p0.w = pkh2(v1.z, v1.w);
            p1.x = pkh2(v2.x, v2.y); p1.y = pkh2(v2.z, v2.w);
            p1.z = pkh2(v3.x, v3.y); p1.w = pkh2(v3.z, v3.w);
            *(uint4*)&Asm[(size_t)kt * 2048 + tid * 8] = p0;
            *(uint4*)&Asm[(size_t)kt * 2048 + 1024 + tid * 8] = p1;
        }
    }

    uint32_t as0 = smem_u32(Asm), bs0 = smem_u32(Bsm);
    float c[4][8][4];
#pragma unroll
    for (int mt = 0; mt < 4; mt++)
#pragma unroll
        for (int nt = 0; nt < 8; nt++)
#pragma unroll
            for (int i = 0; i < 4; i++) c[mt][nt][i] = 0.f;

    uint4 bpre0, bpre1;
    auto load_b = [&](int step) {
        int wt = step >> 4, kt = step & 15;
        const __half* src = &g_wT[(size_t)wt * 32768 + (size_t)tid * 256 + kt * 16];
        bpre0 = *(const uint4*)src;
        bpre1 = *(const uint4*)(src + 8);
    };
    auto store_b = [&](int buf) {
        *(uint4*)&Bsm[(size_t)buf * 2048 + tid * 8] = bpre0;
        *(uint4*)&Bsm[(size_t)buf * 2048 + 1024 + tid * 8] = bpre1;
    };

    load_b(0);
    store_b(0);
    __syncthreads();

    for (int wt = 0; wt < 4; wt++) {
        for (int kt = 0; kt < 16; kt++) {
            int step = wt * 16 + kt;
            int buf = step & 1;
            if (step < 63) load_b(step + 1);
            gemm64(as0 + (uint32_t)kt * 4096u, bs0 + (uint32_t)buf * 4096u,
                   row_base, col_base, lane, c);
            if (step < 63) { store_b(buf ^ 1); __syncthreads(); }
        }
        const float* bias = pb.b[wt];
#pragma unroll
        for (int nt = 0; nt < 8; nt++) {
            int col = col_base + nt * 8 + lc * 2;
            float2 bb = *(const float2*)&bias[col];
#pragma unroll
            for (int mt = 0; mt < 4; mt++) {
                int r0 = row_base + mt * 16 + lr;
                if (r0 < rows)
                    *(unsigned*)&g_yh[(size_t)(m0 + r0) * 512 + wt * 128 + col] =
                        pkh2(c[mt][nt][0] + bb.x, c[mt][nt][1] + bb.y);
                if (r0 + 8 < rows)
                    *(unsigned*)&g_yh[(size_t)(m0 + r0 + 8) * 512 + wt * 128 + col] =
                        pkh2(c[mt][nt][2] + bb.x, c[mt][nt][3] + bb.y);
                c[mt][nt][0] = 0.f; c[mt][nt][1] = 0.f; c[mt][nt][2] = 0.f; c[mt][nt][3] = 0.f;
            }
        }
    }
}

// ---------------- edge GEMM: K=128 (msg @ We_bot) + epilogue g(rt) add ------
#define GST 136   // g-stage smem stride in halves

__global__ __launch_bounds__(128, 2) void k_edge_gemm(const int* __restrict__ src_a,
                                                      const int* __restrict__ e_id,
                                                      const float* __restrict__ edge_t,
                                                      const float* __restrict__ eraw) {
    extern __shared__ __align__(16) char dsm[];
    __half* Bsm = (__half*)dsm;                    // 8 ktiles x 4KB = 32KB (We_bot)
    __half* Gsm = (__half*)dsm;                    // overlay after mainloop: 128 x GST halves
    __half* Asm = (__half*)(dsm + 32768);          // 2 x 4KB double buffer
    __shared__ int eid_s[128];
    __shared__ float relt_s[128];
    const int m0 = blockIdx.x * 128;
    const int tid = threadIdx.x;
    int rows = ME - m0; if (rows > 128) rows = 128;
    {
        int r = (tid < rows ? tid : rows - 1);
        int e = e_id[m0 + r];
        eid_s[tid] = e;
        relt_s[tid] = edge_t[e] - g_lu[src_a[m0 + r]];
    }

    const int warp = tid >> 5, lane = tid & 31;
    const int row_base = (warp & 1) * 64, col_base = (warp >> 1) * 64;
    const int lr = lane >> 2, lc = lane & 3;

    {
        const __half* brow = &g_wT[(size_t)4 * 32768 + (size_t)tid * 256 + 128];
#pragma unroll
        for (int kt = 0; kt < 8; kt++) {
            const __half* src = brow + kt * 16;
            *(uint4*)&Bsm[(size_t)kt * 2048 + tid * 8] = *(const uint4*)src;
            *(uint4*)&Bsm[(size_t)kt * 2048 + 1024 + tid * 8] = *(const uint4*)(src + 8);
        }
    }
    __syncthreads();

    float c[4][8][4];
#pragma unroll
    for (int mt = 0; mt < 4; mt++)
#pragma unroll
        for (int nt = 0; nt < 8; nt++)
#pragma unroll
            for (int i = 0; i < 4; i++) c[mt][nt][i] = 0.f;

    float x = (relt_s[tid] - TLO) * TINV;
    x = fminf(fmaxf(x, 0.0f), (float)(NT - 1) - 1e-3f);
    const int ti = (int)x;
    const float tf = x - (float)ti;
    const float* arow_msg = &eraw[(size_t)eid_s[tid] * 128];
    uint32_t as0 = smem_u32(Asm), bs0 = smem_u32(Bsm);

    float apre[16];
    auto load_a = [&](int ch, float* ap) {
        const float* src = arow_msg + ch * 16;
        float4 v0 = *(const float4*)src;
        float4 v1 = *(const float4*)(src + 4);
        float4 v2 = *(const float4*)(src + 8);
        float4 v3 = *(const float4*)(src + 12);
        ap[0] = v0.x; ap[1] = v0.y; ap[2] = v0.z; ap[3] = v0.w;
        ap[4] = v1.x; ap[5] = v1.y; ap[6] = v1.z; ap[7] = v1.w;
        ap[8] = v2.x; ap[9] = v2.y; ap[10] = v2.z; ap[11] = v2.w;
        ap[12] = v3.x; ap[13] = v3.y; ap[14] = v3.z; ap[15] = v3.w;
    };
    auto store_a = [&](int buf, const float* ap) {
        uint4 p0, p1;
        p0.x = pkh2(ap[0], ap[1]); p0.y = pkh2(ap[2], ap[3]);
        p0.z = pkh2(ap[4], ap[5]); p0.w = pkh2(ap[6], ap[7]);
        p1.x = pkh2(ap[8], ap[9]); p1.y = pkh2(ap[10], ap[11]);
        p1.z = pkh2(ap[12], ap[13]); p1.w = pkh2(ap[14], ap[15]);
        *(uint4*)&Asm[(size_t)buf * 2048 + tid * 8] = p0;
        *(uint4*)&Asm[(size_t)buf * 2048 + 1024 + tid * 8] = p1;
    };

    load_a(0, apre);
    store_a(0, apre);
    __syncthreads();
    for (int ch = 0; ch < 8; ch++) {
        int buf = ch & 1;
        if (ch < 7) load_a(ch + 1, apre);
        gemm64(as0 + (uint32_t)buf * 4096u, bs0 + (uint32_t)ch * 4096u,
               row_base, col_base, lane, c);
        if (ch < 7) { store_a(buf ^ 1, apre); __syncthreads(); }
    }

    __syncthreads();   // Bsm/Asm dead
    {
        const __half* gr0 = &g_tab2[(size_t)ti * 128];
        const __half* gr1 = gr0 + 128;
#pragma unroll
        for (int j = 0; j < 16; j++) {
            uint2 lo = *(const uint2*)(gr0 + j * 8);
            uint2 lo2 = *(const uint2*)(gr0 + j * 8 + 4);
            uint2 hi = *(const uint2*)(gr1 + j * 8);
            uint2 hi2 = *(const uint2*)(gr1 + j * 8 + 4);
            float2 a0 = uph2(lo.x), a1 = uph2(lo.y), a2 = uph2(lo2.x), a3 = uph2(lo2.y);
            float2 b0 = uph2(hi.x), b1 = uph2(hi.y), b2 = uph2(hi2.x), b3 = uph2(hi2.y);
            uint4 o;
            o.x = pkh2(fmaf(tf, b0.x - a0.x, a0.x), fmaf(tf, b0.y - a0.y, a0.y));
            o.y = pkh2(fmaf(tf, b1.x - a1.x, a1.x), fmaf(tf, b1.y - a1.y, a1.y));
            o.z = pkh2(fmaf(tf, b2.x - a2.x, a2.x), fmaf(tf, b2.y - a2.y, a2.y));
            o.w = pkh2(fmaf(tf, b3.x - a3.x, a3.x), fmaf(tf, b3.y - a3.y, a3.y));
            *(uint4*)&Gsm[(size_t)tid * GST + j * 8] = o;
        }
    }
    __syncthreads();

#pragma unroll
    for (int nt = 0; nt < 8; nt++) {
        int col = col_base + nt * 8 + lc * 2;
#pragma unroll
        for (int mt = 0; mt < 4; mt++) {
            int r0 = row_base + mt * 16 + lr;
            if (r0 < rows) {
                float2 gg = uph2(*(unsigned*)&Gsm[(size_t)r0 * GST + col]);
                *(unsigned*)&g_eh[(size_t)(m0 + r0) * 128 + col] =
                    pkh2(c[mt][nt][0] + gg.x, c[mt][nt][1] + gg.y);
            }
            if (r0 + 8 < rows) {
                float2 gg = uph2(*(unsigned*)&Gsm[(size_t)(r0 + 8) * GST + col]);
                *(unsigned*)&g_eh[(size_t)(m0 + r0 + 8) * 128 + col] =
                    pkh2(c[mt][nt][2] + gg.x, c[mt][nt][3] + gg.y);
            }
        }
    }
}

// ---------------- fused attention (fp16 accumulators) -----------------------
__global__ __launch_bounds__(256) void k_attn(const int* __restrict__ src_a,
                                              const int* __restrict__ dst_a) {
    int gw = (blockIdx.x * 256 + threadIdx.x) >> 5;
    int lane = threadIdx.x & 31;
    if (gw >= ME) return;
    int s = src_a[gw], d = dst_a[gw];
    uint2 qu = *(const uint2*)&g_yh[(size_t)d * 512 + lane * 4];
    uint2 ku = *(const uint2*)&g_yh[(size_t)s * 512 + 128 + lane * 4];
    uint2 vu = *(const uint2*)&g_yh[(size_t)s * 512 + 256 + lane * 4];
    uint2 eu = *(const uint2*)&g_eh[(size_t)gw * 128 + lane * 4];
    float2 q0 = uph2(qu.x), q1 = uph2(qu.y);
    float2 k0 = uph2(ku.x), k1 = uph2(ku.y);
    float2 v0 = uph2(vu.x), v1 = uph2(vu.y);
    float2 e0 = uph2(eu.x), e1 = uph2(eu.y);
    float ke0x = k0.x + e0.x, ke0y = k0.y + e0.y, ke1x = k1.x + e1.x, ke1y = k1.y + e1.y;
    float p = q0.x * ke0x + q0.y * ke0y + q1.x * ke1x + q1.y * ke1y;
    p += __shfl_xor_sync(0xffffffffu, p, 8);
    p += __shfl_xor_sync(0xffffffffu, p, 4);
    p += __shfl_xor_sync(0xffffffffu, p, 2);
    p += __shfl_xor_sync(0xffffffffu, p, 1);
    float alpha = __expf(p * 0.125f);   // 1/sqrt(64)
    if ((lane & 15) == 0) atomicAdd(&g_denom[d * 2 + (lane >> 4)], alpha);
    unsigned o0 = pkh2(alpha * (v0.x + e0.x), alpha * (v0.y + e0.y));
    unsigned o1 = pkh2(alpha * (v1.x + e1.x), alpha * (v1.y + e1.y));
    __half* aptr = &g_acc[(size_t)d * 128 + lane * 4];
    asm volatile("red.global.add.noftz.f16x2 [%0], %1;" :: "l"(aptr), "r"(o0) : "memory");
    asm volatile("red.global.add.noftz.f16x2 [%0+4], %1;" :: "l"(aptr), "r"(o1) : "memory");
}

// ---------------- finalize: out = acc/denom + skip --------------------------
__global__ void k_final(float* __restrict__ out) {
    int i = blockIdx.x * 256 + threadIdx.x;
    if (i >= KN * 32) return;
    int node = i >> 5;
    int j4 = (i & 31) * 4;
    int h = j4 >> 6;
    float den = g_denom[node * 2 + h];
    float inv = den > 0.f ? 1.f / den : 0.f;
    uint2 au = *(const uint2*)&g_acc[(size_t)node * 128 + j4];
    float2 a0 = uph2(au.x), a1 = uph2(au.y);
    uint2 sku = *(const uint2*)&g_yh[(size_t)node * 512 + 384 + j4];
    float2 s0 = uph2(sku.x), s1 = uph2(sku.y);
    float4 u;
    u.x = a0.x * inv + s0.x;
    u.y = a0.y * inv + s0.y;
    u.z = a1.x * inv + s1.x;
    u.w = a1.y * inv + s1.y;
    *(float4*)&out[(size_t)node * 128 + j4] = u;
}

// ---------------- launch -----------------------------------------------------
#define NODE_SMEM (65536 + 8192)
#define EDGE_SMEM (32768 + 8192)
#define TABG_SMEM (32768 + 8192)

extern "C" void kernel_launch(void* const* d_in, const int* in_sizes, int n_in,
                              void* d_out, int out_size) {
    (void)in_sizes; (void)n_in; (void)out_size;
    const int*   n_id    = (const int*)d_in[0];
    const int*   eib     = (const int*)d_in[1];   // [2, M]: src then dst
    const int*   e_id    = (const int*)d_in[2];
    const float* nfeat   = (const float*)d_in[4];
    const float* eraw    = (const float*)d_in[5];
    const float* edge_t  = (const float*)d_in[6];
    const float* memv    = (const float*)d_in[7];
    const float* last_up = (const float*)d_in[8];
    const float* w_t     = (const float*)d_in[9];
    const float* b_t     = (const float*)d_in[10];
    const float* Wq = (const float*)d_in[11];
    const float* Wk = (const float*)d_in[13];
    const float* Wv = (const float*)d_in[15];
    const float* We = (const float*)d_in[17];
    const float* Wskip = (const float*)d_in[18];
    NodeB pb;
    pb.b[0] = (const float*)d_in[12];
    pb.b[1] = (const float*)d_in[14];
    pb.b[2] = (const float*)d_in[16];
    pb.b[3] = (const float*)d_in[19];
    float* out = (float*)d_out;

    cudaFuncSetAttribute(k_node_fused, cudaFuncAttributeMaxDynamicSharedMemorySize, NODE_SMEM);
    cudaFuncSetAttribute(k_edge_gemm, cudaFuncAttributeMaxDynamicSharedMemorySize, EDGE_SMEM);
    cudaFuncSetAttribute(k_tabg, cudaFuncAttributeMaxDynamicSharedMemorySize, TABG_SMEM);

    k_prep<<<(5 * 32768 + 255) / 256, 256>>>(Wq, Wk, Wv, Wskip, We);
    k_tab<<<(NT * 128 + 255) / 256, 256>>>(w_t, b_t);
    k_tabg<<<NT / 128, 128, TABG_SMEM>>>();
    k_init<<<(KN * 16 + 255) / 256, 256>>>(last_up, n_id);
    k_node_fused<<<(KN + 127) / 128, 128, NODE_SMEM>>>(n_id, memv, nfeat, pb);
    k_edge_gemm<<<(ME + 127) / 128, 128, EDGE_SMEM>>>(eib, e_id, edge_t, eraw);
    k_attn<<<ME / 8, 256>>>(eib, eib + ME);
    k_final<<<(KN * 32 + 255) / 256, 256>>>(out);
}